// round 2
// baseline (speedup 1.0000x reference)
#include <cuda_runtime.h>
#include <cuda_bf16.h>
#include <math.h>
#include <stddef.h>

// Problem constants
#define BB    4
#define TT    2048
#define DD    1024
#define NH    16
#define DKH   64
#define DFF   4096
#define ROWS  (BB*TT)          // 8192

// ---------------- scratch (static device globals; no allocation allowed) ----
__device__ float g_h  [ (size_t)ROWS * DD ];
__device__ float g_q  [ (size_t)ROWS * DD ];
__device__ float g_k  [ (size_t)ROWS * DD ];
__device__ float g_v  [ (size_t)ROWS * DD ];
__device__ float g_att[ (size_t)ROWS * DD ];
__device__ float g_x2 [ (size_t)ROWS * DD ];
__device__ float g_ff [ (size_t)ROWS * DFF ];

// ---------------- block reduction helper ------------------------------------
__device__ __forceinline__ float block_sum256(float v) {
    __shared__ float red[8];
    #pragma unroll
    for (int off = 16; off; off >>= 1)
        v += __shfl_xor_sync(0xffffffffu, v, off);
    if ((threadIdx.x & 31) == 0) red[threadIdx.x >> 5] = v;
    __syncthreads();
    if (threadIdx.x < 32) {
        float t = (threadIdx.x < 8) ? red[threadIdx.x] : 0.0f;
        #pragma unroll
        for (int off = 4; off; off >>= 1)
            t += __shfl_xor_sync(0xffffffffu, t, off);
        if (threadIdx.x == 0) red[0] = t;
    }
    __syncthreads();
    float r = red[0];
    __syncthreads();   // allow helper reuse
    return r;
}

// ---------------- LayerNorm: one block per row (D=1024, 256 thr, float4) ----
__global__ __launch_bounds__(256)
void ln_kernel(const float* __restrict__ x, const float* __restrict__ g,
               const float* __restrict__ b, float* __restrict__ o)
{
    const int row = blockIdx.x;
    const int tid = threadIdx.x;
    const float* xr = x + (size_t)row * DD;
    float4 v = *(const float4*)(xr + tid * 4);

    float s = v.x + v.y + v.z + v.w;
    float mean = block_sum256(s) * (1.0f / DD);

    float dx = v.x - mean, dy = v.y - mean, dz = v.z - mean, dw = v.w - mean;
    float ss = dx*dx + dy*dy + dz*dz + dw*dw;
    float var = block_sum256(ss) * (1.0f / DD);
    float rstd = rsqrtf(var + 1e-5f);

    float4 gv = *(const float4*)(g + tid * 4);
    float4 bv = *(const float4*)(b + tid * 4);
    float4 ov;
    ov.x = dx * rstd * gv.x + bv.x;
    ov.y = dy * rstd * gv.y + bv.y;
    ov.z = dz * rstd * gv.z + bv.z;
    ov.w = dw * rstd * gv.w + bv.w;
    *(float4*)(o + (size_t)row * DD + tid * 4) = ov;
}

// ---------------- NT GEMM: C[M,N] = A[M,K] @ B[N,K]^T + bias (+res)(+gelu) --
// 128x128 block tile, BK=8, 256 threads, split 8x8 microtile (2x2 of 4x4).
__global__ __launch_bounds__(256)
void gemm_nt(const float* __restrict__ A, const float* __restrict__ B,
             const float* __restrict__ bias, const float* __restrict__ R,
             float* __restrict__ C, int M, int Nc, int K, int gelu)
{
    __shared__ float As[8][128];
    __shared__ float Bs[8][128];

    const int tid = threadIdx.x;
    const int bm = blockIdx.y * 128;
    const int bn = blockIdx.x * 128;
    const int tx = tid & 15;        // n quad
    const int ty = tid >> 4;        // m quad
    const int lr = tid >> 1;        // 0..127 (tile row to load)
    const int lc = (tid & 1) << 2;  // 0 or 4 (k offset, float4)

    const float* Ald = A + (size_t)(bm + lr) * K + lc;
    const float* Bld = B + (size_t)(bn + lr) * K + lc;

    float acc[2][2][4][4] = {};

    for (int k0 = 0; k0 < K; k0 += 8) {
        float4 av = *(const float4*)(Ald + k0);
        float4 bv = *(const float4*)(Bld + k0);
        __syncthreads();   // previous iteration's compute done
        As[lc+0][lr] = av.x; As[lc+1][lr] = av.y;
        As[lc+2][lr] = av.z; As[lc+3][lr] = av.w;
        Bs[lc+0][lr] = bv.x; Bs[lc+1][lr] = bv.y;
        Bs[lc+2][lr] = bv.z; Bs[lc+3][lr] = bv.w;
        __syncthreads();

        #pragma unroll
        for (int kk = 0; kk < 8; kk++) {
            float4 a0 = *(const float4*)&As[kk][ty * 4];
            float4 a1 = *(const float4*)&As[kk][64 + ty * 4];
            float4 b0 = *(const float4*)&Bs[kk][tx * 4];
            float4 b1 = *(const float4*)&Bs[kk][64 + tx * 4];
            float ar[2][4] = {{a0.x, a0.y, a0.z, a0.w}, {a1.x, a1.y, a1.z, a1.w}};
            float br[2][4] = {{b0.x, b0.y, b0.z, b0.w}, {b1.x, b1.y, b1.z, b1.w}};
            #pragma unroll
            for (int bi = 0; bi < 2; bi++)
                #pragma unroll
                for (int bj = 0; bj < 2; bj++)
                    #pragma unroll
                    for (int i = 0; i < 4; i++)
                        #pragma unroll
                        for (int j = 0; j < 4; j++)
                            acc[bi][bj][i][j] += ar[bi][i] * br[bj][j];
        }
    }

    #pragma unroll
    for (int bi = 0; bi < 2; bi++) {
        #pragma unroll
        for (int i = 0; i < 4; i++) {
            const int m = bm + bi * 64 + ty * 4 + i;
            #pragma unroll
            for (int bj = 0; bj < 2; bj++) {
                #pragma unroll
                for (int j = 0; j < 4; j++) {
                    const int n = bn + bj * 64 + tx * 4 + j;
                    float val = acc[bi][bj][i][j] + bias[n];
                    if (R) val += R[(size_t)m * Nc + n];
                    if (gelu) val = 0.5f * val * (1.0f + erff(val * 0.70710678118654752f));
                    C[(size_t)m * Nc + n] = val;
                }
            }
        }
    }
}

// ---------------- RoPE (in place on [ROWS, D], per-head pairs) --------------
__global__ __launch_bounds__(256)
void rope_kernel(float* __restrict__ x)
{
    const int idx  = blockIdx.x * blockDim.x + threadIdx.x; // over ROWS*D/2
    const int pair = idx & 511;        // D/2 - 1
    const int row  = idx >> 9;
    const int t    = row & (TT - 1);
    const int i    = pair & 31;        // pair index within head (dk/2 = 32)
    // theta_i = 10000^(-2i/64) = exp(-ln(1e4)/32 * i)
    const float ang = (float)t * expf(-0.28782313662425537f * (float)i);
    float s, c;
    sincosf(ang, &s, &c);
    float2* p = (float2*)(x + ((size_t)row << 10) + (pair << 1));
    float2 v = *p;
    float2 o;
    o.x = v.x * c - v.y * s;
    o.y = v.x * s + v.y * c;
    *p = o;
}

// ---------------- flash-style attention -------------------------------------
// One block per (b, head, 16-query tile). Online softmax over 64-wide tiles.
#define QB 16
#define SB 64

__global__ __launch_bounds__(256)
void attn_kernel(const float* __restrict__ Q, const float* __restrict__ K,
                 const float* __restrict__ V, const unsigned char* __restrict__ mask,
                 float* __restrict__ O)
{
    __shared__ float Qs[QB][DKH];       // 4KB
    __shared__ float KsT[DKH][SB + 4];  // transposed, padded: 17KB
    __shared__ float Vs[SB][DKH];       // 16KB
    __shared__ float Ps[QB][SB];        // 4KB
    __shared__ unsigned char Ms[SB];

    const int tid = threadIdx.x;
    const int qt  = blockIdx.x;   // 0..T/QB-1
    const int hh  = blockIdx.y;   // head
    const int bb  = blockIdx.z;   // batch
    const int q0  = qt * QB;
    const size_t base = ((size_t)bb * TT) * DD + (size_t)hh * DKH;

    // load Q tile: 16x64 floats = 256 float4 (one per thread)
    {
        int r = tid >> 4, c4 = (tid & 15) << 2;
        *(float4*)&Qs[r][c4] =
            *(const float4*)(Q + base + (size_t)(q0 + r) * DD + c4);
    }

    const int qi = tid >> 4;          // query row 0..15
    const int x4 = (tid & 15) << 2;   // s4 in score phase / d4 in value phase

    float m_run = -INFINITY, l_run = 0.0f;
    float acc0 = 0.f, acc1 = 0.f, acc2 = 0.f, acc3 = 0.f;

    for (int s0 = 0; s0 < TT; s0 += SB) {
        __syncthreads();
        // load K (transposed) and V tiles: 64x64 each, 4 float4 per thread
        #pragma unroll
        for (int it = 0; it < 4; it++) {
            int li = tid + it * 256;
            int s = li >> 4, c4 = (li & 15) << 2;
            float4 kv = *(const float4*)(K + base + (size_t)(s0 + s) * DD + c4);
            KsT[c4+0][s] = kv.x; KsT[c4+1][s] = kv.y;
            KsT[c4+2][s] = kv.z; KsT[c4+3][s] = kv.w;
            *(float4*)&Vs[s][c4] =
                *(const float4*)(V + base + (size_t)(s0 + s) * DD + c4);
        }
        if (tid < SB) Ms[tid] = mask[(size_t)bb * TT + s0 + tid];
        __syncthreads();

        // scores: thread (qi, x4) computes 4 dot products of length 64
        float sc[4] = {0.f, 0.f, 0.f, 0.f};
        #pragma unroll
        for (int d0 = 0; d0 < DKH; d0 += 4) {
            float4 qv = *(const float4*)&Qs[qi][d0];
            float qa[4] = {qv.x, qv.y, qv.z, qv.w};
            #pragma unroll
            for (int dd = 0; dd < 4; dd++) {
                float4 kv = *(const float4*)&KsT[d0 + dd][x4];
                sc[0] += qa[dd] * kv.x;
                sc[1] += qa[dd] * kv.y;
                sc[2] += qa[dd] * kv.z;
                sc[3] += qa[dd] * kv.w;
            }
        }
        #pragma unroll
        for (int j = 0; j < 4; j++) {
            sc[j] *= 0.125f;                       // 1/sqrt(64)
            if (Ms[x4 + j]) sc[j] = -INFINITY;
        }

        // row max across the 16 lanes owning this query row
        float mt = fmaxf(fmaxf(sc[0], sc[1]), fmaxf(sc[2], sc[3]));
        #pragma unroll
        for (int off = 8; off; off >>= 1)
            mt = fmaxf(mt, __shfl_xor_sync(0xffffffffu, mt, off));

        float m_new = fmaxf(m_run, mt);
        float alpha = expf(m_run - m_new);

        float ps = 0.f;
        #pragma unroll
        for (int j = 0; j < 4; j++) {
            sc[j] = expf(sc[j] - m_new);
            ps += sc[j];
            Ps[qi][x4 + j] = sc[j];
        }
        #pragma unroll
        for (int off = 8; off; off >>= 1)
            ps += __shfl_xor_sync(0xffffffffu, ps, off);

        l_run = l_run * alpha + ps;
        m_run = m_new;
        acc0 *= alpha; acc1 *= alpha; acc2 *= alpha; acc3 *= alpha;
        __syncwarp();

        // value accumulation: thread (qi, x4) owns 4 output dims
        #pragma unroll 8
        for (int s = 0; s < SB; s++) {
            float p = Ps[qi][s];
            float4 vv = *(const float4*)&Vs[s][x4];
            acc0 += p * vv.x;
            acc1 += p * vv.y;
            acc2 += p * vv.z;
            acc3 += p * vv.w;
        }
    }

    const float inv = 1.0f / l_run;
    float4 o;
    o.x = acc0 * inv; o.y = acc1 * inv; o.z = acc2 * inv; o.w = acc3 * inv;
    *(float4*)(O + base + (size_t)(q0 + qi) * DD + x4) = o;
}

// ---------------- launch ----------------------------------------------------
extern "C" void kernel_launch(void* const* d_in, const int* in_sizes, int n_in,
                              void* d_out, int out_size)
{
    const float* x   = (const float*)d_in[0];
    const unsigned char* mask = (const unsigned char*)d_in[1];
    const float* Wq  = (const float*)d_in[2];
    const float* bq  = (const float*)d_in[3];
    const float* Wk  = (const float*)d_in[4];
    const float* bk  = (const float*)d_in[5];
    const float* Wv  = (const float*)d_in[6];
    const float* bv  = (const float*)d_in[7];
    const float* Wo  = (const float*)d_in[8];
    const float* bo  = (const float*)d_in[9];
    const float* W1  = (const float*)d_in[10];
    const float* b1  = (const float*)d_in[11];
    const float* W2  = (const float*)d_in[12];
    const float* b2  = (const float*)d_in[13];
    const float* g1  = (const float*)d_in[14];
    const float* be1 = (const float*)d_in[15];
    const float* g2  = (const float*)d_in[16];
    const float* be2 = (const float*)d_in[17];
    float* out = (float*)d_out;

    float *h, *q, *k, *v, *att, *x2, *ff;
    cudaGetSymbolAddress((void**)&h,   g_h);
    cudaGetSymbolAddress((void**)&q,   g_q);
    cudaGetSymbolAddress((void**)&k,   g_k);
    cudaGetSymbolAddress((void**)&v,   g_v);
    cudaGetSymbolAddress((void**)&att, g_att);
    cudaGetSymbolAddress((void**)&x2,  g_x2);
    cudaGetSymbolAddress((void**)&ff,  g_ff);

    const dim3 gD (DD  / 128, ROWS / 128);   // (8,64)
    const dim3 gDF(DFF / 128, ROWS / 128);   // (32,64)

    // 1) h = LN(x)
    ln_kernel<<<ROWS, 256>>>(x, g1, be1, h);
    // 2) q,k,v projections
    gemm_nt<<<gD, 256>>>(h, Wq, bq, nullptr, q, ROWS, DD, DD, 0);
    gemm_nt<<<gD, 256>>>(h, Wk, bk, nullptr, k, ROWS, DD, DD, 0);
    gemm_nt<<<gD, 256>>>(h, Wv, bv, nullptr, v, ROWS, DD, DD, 0);
    // 3) rope on q, k (in place)
    rope_kernel<<<(ROWS * DD / 2) / 256, 256>>>(q);
    rope_kernel<<<(ROWS * DD / 2) / 256, 256>>>(k);
    // 4) attention
    attn_kernel<<<dim3(TT / QB, NH, BB), 256>>>(q, k, v, mask, att);
    // 5) x2 = x + att @ Wo^T + bo
    gemm_nt<<<gD, 256>>>(att, Wo, bo, x, x2, ROWS, DD, DD, 0);
    // 6) h = LN(x2)
    ln_kernel<<<ROWS, 256>>>(x2, g2, be2, h);
    // 7) ff = gelu(h @ W1^T + b1)
    gemm_nt<<<gDF, 256>>>(h, W1, b1, nullptr, ff, ROWS, DFF, DD, 1);
    // 8) out = x2 + ff @ W2^T + b2
    gemm_nt<<<gD, 256>>>(ff, W2, b2, x2, out, ROWS, DD, DFF, 0);
}

// round 5
// speedup vs baseline: 1.2499x; 1.2499x over previous
#include <cuda_runtime.h>
#include <cuda_bf16.h>
#include <math.h>
#include <stddef.h>
#include <stdint.h>

// Problem constants
#define BB    4
#define TT    2048
#define DD    1024
#define NH    16
#define DKH   64
#define DFF   4096
#define ROWS  (BB*TT)          // 8192

// ---------------- scratch (static device globals; no allocation allowed) ----
__device__ float g_h  [ (size_t)ROWS * DD ];
__device__ float g_q  [ (size_t)ROWS * DD ];
__device__ float g_k  [ (size_t)ROWS * DD ];
__device__ float g_v  [ (size_t)ROWS * DD ];
__device__ float g_att[ (size_t)ROWS * DD ];
__device__ float g_x2 [ (size_t)ROWS * DD ];
__device__ float g_ff [ (size_t)ROWS * DFF ];

// ==================== warp-level bf16 MMA GEMM ==============================
// C[M,N] = A[M,K] @ B[N,K]^T + bias (+res)(+gelu)
// bf16 hi/lo split: C = Ah*Bh + Ah*Bl + Al*Bh  (fp32 accumulate)
// Block 128x128, BK=32, 256 threads = 8 warps, warp tile 32x64.
#define BM 128
#define BN 128
#define BK 32
#define LDS_PAD 40   // 32 + 8 bf16 padding

__device__ __forceinline__ void mma16816(float* c, const uint32_t* a, const uint32_t* b) {
    asm volatile(
        "mma.sync.aligned.m16n8k16.row.col.f32.bf16.bf16.f32 "
        "{%0,%1,%2,%3}, {%4,%5,%6,%7}, {%8,%9}, {%0,%1,%2,%3};"
        : "+f"(c[0]), "+f"(c[1]), "+f"(c[2]), "+f"(c[3])
        : "r"(a[0]), "r"(a[1]), "r"(a[2]), "r"(a[3]), "r"(b[0]), "r"(b[1]));
}

__device__ __forceinline__ uint32_t pack_hi(float x, float y,
                                            __nv_bfloat16& hx, __nv_bfloat16& hy) {
    hx = __float2bfloat16(x); hy = __float2bfloat16(y);
    __nv_bfloat162 p = {hx, hy};
    return *(uint32_t*)&p;
}

__global__ __launch_bounds__(256)
void gemm_mma(const float* __restrict__ A, const float* __restrict__ B,
              const float* __restrict__ bias, const float* __restrict__ R,
              float* __restrict__ C, int Nc, int K, int gelu)
{
    __shared__ __nv_bfloat16 Ah[BM][LDS_PAD];
    __shared__ __nv_bfloat16 Al[BM][LDS_PAD];
    __shared__ __nv_bfloat16 Bh[BN][LDS_PAD];
    __shared__ __nv_bfloat16 Bl[BN][LDS_PAD];

    const int tid  = threadIdx.x;
    const int wid  = tid >> 5;
    const int lane = tid & 31;
    const int g    = lane >> 2;     // group 0..7
    const int tg   = lane & 3;      // thread-in-group 0..3
    const int wm0  = (wid & 3) * 32;    // warp m offset
    const int wn0  = (wid >> 2) * 64;   // warp n offset
    const int bm   = blockIdx.y * BM;
    const int bn   = blockIdx.x * BN;

    // loader: thread t handles row t>>1, 16 cols starting at (t&1)*16
    const int lrow = tid >> 1;
    const int lcol = (tid & 1) * 16;
    const float* Ald = A + (size_t)(bm + lrow) * K + lcol;
    const float* Bld = B + (size_t)(bn + lrow) * K + lcol;

    float acc[2][8][4] = {};
    const int NIT = K / BK;

    float4 apre[4], bpre[4];
    #pragma unroll
    for (int i = 0; i < 4; i++) { apre[i] = *(const float4*)(Ald + i * 4);
                                  bpre[i] = *(const float4*)(Bld + i * 4); }

    for (int iter = 0; iter < NIT; iter++) {
        __syncthreads();   // previous compute reads done
        #pragma unroll
        for (int i = 0; i < 4; i++) {
            float4 av = apre[i], bv = bpre[i];
            __nv_bfloat16 h0, h1, h2, h3;
            uint32_t u01 = pack_hi(av.x, av.y, h0, h1);
            uint32_t u23 = pack_hi(av.z, av.w, h2, h3);
            *(uint32_t*)&Ah[lrow][lcol + i*4]     = u01;
            *(uint32_t*)&Ah[lrow][lcol + i*4 + 2] = u23;
            __nv_bfloat162 l01 = { __float2bfloat16(av.x - __bfloat162float(h0)),
                                   __float2bfloat16(av.y - __bfloat162float(h1)) };
            __nv_bfloat162 l23 = { __float2bfloat16(av.z - __bfloat162float(h2)),
                                   __float2bfloat16(av.w - __bfloat162float(h3)) };
            *(uint32_t*)&Al[lrow][lcol + i*4]     = *(uint32_t*)&l01;
            *(uint32_t*)&Al[lrow][lcol + i*4 + 2] = *(uint32_t*)&l23;

            u01 = pack_hi(bv.x, bv.y, h0, h1);
            u23 = pack_hi(bv.z, bv.w, h2, h3);
            *(uint32_t*)&Bh[lrow][lcol + i*4]     = u01;
            *(uint32_t*)&Bh[lrow][lcol + i*4 + 2] = u23;
            __nv_bfloat162 m01 = { __float2bfloat16(bv.x - __bfloat162float(h0)),
                                   __float2bfloat16(bv.y - __bfloat162float(h1)) };
            __nv_bfloat162 m23 = { __float2bfloat16(bv.z - __bfloat162float(h2)),
                                   __float2bfloat16(bv.w - __bfloat162float(h3)) };
            *(uint32_t*)&Bl[lrow][lcol + i*4]     = *(uint32_t*)&m01;
            *(uint32_t*)&Bl[lrow][lcol + i*4 + 2] = *(uint32_t*)&m23;
        }
        __syncthreads();

        if (iter + 1 < NIT) {
            const float* An = Ald + (iter + 1) * BK;
            const float* Bn = Bld + (iter + 1) * BK;
            #pragma unroll
            for (int i = 0; i < 4; i++) { apre[i] = *(const float4*)(An + i * 4);
                                          bpre[i] = *(const float4*)(Bn + i * 4); }
        }

        #pragma unroll
        for (int k0 = 0; k0 < BK; k0 += 16) {
            // A fragments (hi & lo) for 2 m16 tiles
            uint32_t afh[2][4], afl[2][4];
            #pragma unroll
            for (int mi = 0; mi < 2; mi++) {
                const int r0 = wm0 + mi * 16 + g;
                const int c0 = k0 + tg * 2;
                afh[mi][0] = *(const uint32_t*)&Ah[r0    ][c0    ];
                afh[mi][1] = *(const uint32_t*)&Ah[r0 + 8][c0    ];
                afh[mi][2] = *(const uint32_t*)&Ah[r0    ][c0 + 8];
                afh[mi][3] = *(const uint32_t*)&Ah[r0 + 8][c0 + 8];
                afl[mi][0] = *(const uint32_t*)&Al[r0    ][c0    ];
                afl[mi][1] = *(const uint32_t*)&Al[r0 + 8][c0    ];
                afl[mi][2] = *(const uint32_t*)&Al[r0    ][c0 + 8];
                afl[mi][3] = *(const uint32_t*)&Al[r0 + 8][c0 + 8];
            }
            #pragma unroll
            for (int ni = 0; ni < 8; ni++) {
                const int nr = wn0 + ni * 8 + g;
                const int kc = k0 + tg * 2;
                uint32_t bfh[2], bfl[2];
                bfh[0] = *(const uint32_t*)&Bh[nr][kc    ];
                bfh[1] = *(const uint32_t*)&Bh[nr][kc + 8];
                bfl[0] = *(const uint32_t*)&Bl[nr][kc    ];
                bfl[1] = *(const uint32_t*)&Bl[nr][kc + 8];
                #pragma unroll
                for (int mi = 0; mi < 2; mi++) {
                    mma16816(acc[mi][ni], afh[mi], bfh);
                    mma16816(acc[mi][ni], afh[mi], bfl);
                    mma16816(acc[mi][ni], afl[mi], bfh);
                }
            }
        }
    }

    // epilogue: fragment layout c0:(g, tg*2) c1:(g, tg*2+1) c2:(g+8,..) c3
    #pragma unroll
    for (int mi = 0; mi < 2; mi++) {
        #pragma unroll
        for (int ni = 0; ni < 8; ni++) {
            const int n  = bn + wn0 + ni * 8 + tg * 2;
            const float bs0 = __ldg(bias + n), bs1 = __ldg(bias + n + 1);
            #pragma unroll
            for (int half = 0; half < 2; half++) {
                const int m = bm + wm0 + mi * 16 + g + half * 8;
                float v0 = acc[mi][ni][half * 2]     + bs0;
                float v1 = acc[mi][ni][half * 2 + 1] + bs1;
                if (R) {
                    const float* Rp = R + (size_t)m * Nc + n;
                    v0 += Rp[0]; v1 += Rp[1];
                }
                if (gelu) {
                    v0 = 0.5f * v0 * (1.0f + erff(v0 * 0.70710678118654752f));
                    v1 = 0.5f * v1 * (1.0f + erff(v1 * 0.70710678118654752f));
                }
                float2 o = { v0, v1 };
                *(float2*)(C + (size_t)m * Nc + n) = o;
            }
        }
    }
}

// ---------------- block reduction helper ------------------------------------
__device__ __forceinline__ float block_sum256(float v) {
    __shared__ float red[8];
    #pragma unroll
    for (int off = 16; off; off >>= 1)
        v += __shfl_xor_sync(0xffffffffu, v, off);
    if ((threadIdx.x & 31) == 0) red[threadIdx.x >> 5] = v;
    __syncthreads();
    if (threadIdx.x < 32) {
        float t = (threadIdx.x < 8) ? red[threadIdx.x] : 0.0f;
        #pragma unroll
        for (int off = 4; off; off >>= 1)
            t += __shfl_xor_sync(0xffffffffu, t, off);
        if (threadIdx.x == 0) red[0] = t;
    }
    __syncthreads();
    float r = red[0];
    __syncthreads();
    return r;
}

// ---------------- LayerNorm --------------------------------------------------
__global__ __launch_bounds__(256)
void ln_kernel(const float* __restrict__ x, const float* __restrict__ g,
               const float* __restrict__ b, float* __restrict__ o)
{
    const int row = blockIdx.x;
    const int tid = threadIdx.x;
    const float* xr = x + (size_t)row * DD;
    float4 v = *(const float4*)(xr + tid * 4);

    float s = v.x + v.y + v.z + v.w;
    float mean = block_sum256(s) * (1.0f / DD);

    float dx = v.x - mean, dy = v.y - mean, dz = v.z - mean, dw = v.w - mean;
    float ss = dx*dx + dy*dy + dz*dz + dw*dw;
    float var = block_sum256(ss) * (1.0f / DD);
    float rstd = rsqrtf(var + 1e-5f);

    float4 gv = *(const float4*)(g + tid * 4);
    float4 bv = *(const float4*)(b + tid * 4);
    float4 ov;
    ov.x = dx * rstd * gv.x + bv.x;
    ov.y = dy * rstd * gv.y + bv.y;
    ov.z = dz * rstd * gv.z + bv.z;
    ov.w = dw * rstd * gv.w + bv.w;
    *(float4*)(o + (size_t)row * DD + tid * 4) = ov;
}

// ---------------- RoPE -------------------------------------------------------
__global__ __launch_bounds__(256)
void rope_kernel(float* __restrict__ x)
{
    const int idx  = blockIdx.x * blockDim.x + threadIdx.x;
    const int pair = idx & 511;
    const int row  = idx >> 9;
    const int t    = row & (TT - 1);
    const int i    = pair & 31;
    const float ang = (float)t * expf(-0.28782313662425537f * (float)i);
    float s, c;
    sincosf(ang, &s, &c);
    float2* p = (float2*)(x + ((size_t)row << 10) + (pair << 1));
    float2 v = *p;
    float2 o;
    o.x = v.x * c - v.y * s;
    o.y = v.x * s + v.y * c;
    *p = o;
}

// ---------------- flash-style attention --------------------------------------
#define QB 16
#define SB 64

__global__ __launch_bounds__(256)
void attn_kernel(const float* __restrict__ Q, const float* __restrict__ K,
                 const float* __restrict__ V, const unsigned char* __restrict__ mask,
                 float* __restrict__ O)
{
    __shared__ float Qs[QB][DKH];
    __shared__ float KsT[DKH][SB + 4];
    __shared__ float Vs[SB][DKH];
    __shared__ float Ps[QB][SB];
    __shared__ unsigned char Ms[SB];

    const int tid = threadIdx.x;
    const int qt  = blockIdx.x;
    const int hh  = blockIdx.y;
    const int bb  = blockIdx.z;
    const int q0  = qt * QB;
    const size_t base = ((size_t)bb * TT) * DD + (size_t)hh * DKH;

    {
        int r = tid >> 4, c4 = (tid & 15) << 2;
        *(float4*)&Qs[r][c4] =
            *(const float4*)(Q + base + (size_t)(q0 + r) * DD + c4);
    }

    const int qi = tid >> 4;
    const int x4 = (tid & 15) << 2;

    float m_run = -INFINITY, l_run = 0.0f;
    float acc0 = 0.f, acc1 = 0.f, acc2 = 0.f, acc3 = 0.f;

    for (int s0 = 0; s0 < TT; s0 += SB) {
        __syncthreads();
        #pragma unroll
        for (int it = 0; it < 4; it++) {
            int li = tid + it * 256;
            int s = li >> 4, c4 = (li & 15) << 2;
            float4 kv = *(const float4*)(K + base + (size_t)(s0 + s) * DD + c4);
            KsT[c4+0][s] = kv.x; KsT[c4+1][s] = kv.y;
            KsT[c4+2][s] = kv.z; KsT[c4+3][s] = kv.w;
            *(float4*)&Vs[s][c4] =
                *(const float4*)(V + base + (size_t)(s0 + s) * DD + c4);
        }
        if (tid < SB) Ms[tid] = mask[(size_t)bb * TT + s0 + tid];
        __syncthreads();

        float sc[4] = {0.f, 0.f, 0.f, 0.f};
        #pragma unroll
        for (int d0 = 0; d0 < DKH; d0 += 4) {
            float4 qv = *(const float4*)&Qs[qi][d0];
            float qa[4] = {qv.x, qv.y, qv.z, qv.w};
            #pragma unroll
            for (int dd = 0; dd < 4; dd++) {
                float4 kv = *(const float4*)&KsT[d0 + dd][x4];
                sc[0] += qa[dd] * kv.x;
                sc[1] += qa[dd] * kv.y;
                sc[2] += qa[dd] * kv.z;
                sc[3] += qa[dd] * kv.w;
            }
        }
        #pragma unroll
        for (int j = 0; j < 4; j++) {
            sc[j] *= 0.125f;
            if (Ms[x4 + j]) sc[j] = -INFINITY;
        }

        float mt = fmaxf(fmaxf(sc[0], sc[1]), fmaxf(sc[2], sc[3]));
        #pragma unroll
        for (int off = 8; off; off >>= 1)
            mt = fmaxf(mt, __shfl_xor_sync(0xffffffffu, mt, off));

        float m_new = fmaxf(m_run, mt);
        float alpha = expf(m_run - m_new);

        float ps = 0.f;
        #pragma unroll
        for (int j = 0; j < 4; j++) {
            sc[j] = expf(sc[j] - m_new);
            ps += sc[j];
            Ps[qi][x4 + j] = sc[j];
        }
        #pragma unroll
        for (int off = 8; off; off >>= 1)
            ps += __shfl_xor_sync(0xffffffffu, ps, off);

        l_run = l_run * alpha + ps;
        m_run = m_new;
        acc0 *= alpha; acc1 *= alpha; acc2 *= alpha; acc3 *= alpha;
        __syncwarp();

        #pragma unroll 8
        for (int s = 0; s < SB; s++) {
            float p = Ps[qi][s];
            float4 vv = *(const float4*)&Vs[s][x4];
            acc0 += p * vv.x;
            acc1 += p * vv.y;
            acc2 += p * vv.z;
            acc3 += p * vv.w;
        }
    }

    const float inv = 1.0f / l_run;
    float4 o;
    o.x = acc0 * inv; o.y = acc1 * inv; o.z = acc2 * inv; o.w = acc3 * inv;
    *(float4*)(O + base + (size_t)(q0 + qi) * DD + x4) = o;
}

// ---------------- launch ----------------------------------------------------
extern "C" void kernel_launch(void* const* d_in, const int* in_sizes, int n_in,
                              void* d_out, int out_size)
{
    const float* x   = (const float*)d_in[0];
    const unsigned char* mask = (const unsigned char*)d_in[1];
    const float* Wq  = (const float*)d_in[2];
    const float* bq  = (const float*)d_in[3];
    const float* Wk  = (const float*)d_in[4];
    const float* bk  = (const float*)d_in[5];
    const float* Wv  = (const float*)d_in[6];
    const float* bv  = (const float*)d_in[7];
    const float* Wo  = (const float*)d_in[8];
    const float* bo  = (const float*)d_in[9];
    const float* W1  = (const float*)d_in[10];
    const float* b1  = (const float*)d_in[11];
    const float* W2  = (const float*)d_in[12];
    const float* b2  = (const float*)d_in[13];
    const float* g1  = (const float*)d_in[14];
    const float* be1 = (const float*)d_in[15];
    const float* g2  = (const float*)d_in[16];
    const float* be2 = (const float*)d_in[17];
    float* out = (float*)d_out;

    float *h, *q, *k, *v, *att, *x2, *ff;
    cudaGetSymbolAddress((void**)&h,   g_h);
    cudaGetSymbolAddress((void**)&q,   g_q);
    cudaGetSymbolAddress((void**)&k,   g_k);
    cudaGetSymbolAddress((void**)&v,   g_v);
    cudaGetSymbolAddress((void**)&att, g_att);
    cudaGetSymbolAddress((void**)&x2,  g_x2);
    cudaGetSymbolAddress((void**)&ff,  g_ff);

    const dim3 gD (DD  / BN, ROWS / BM);   // (8,64)
    const dim3 gDF(DFF / BN, ROWS / BM);   // (32,64)

    // 1) h = LN(x)
    ln_kernel<<<ROWS, 256>>>(x, g1, be1, h);
    // 2) q,k,v projections
    gemm_mma<<<gD, 256>>>(h, Wq, bq, nullptr, q, DD, DD, 0);
    gemm_mma<<<gD, 256>>>(h, Wk, bk, nullptr, k, DD, DD, 0);
    gemm_mma<<<gD, 256>>>(h, Wv, bv, nullptr, v, DD, DD, 0);
    // 3) rope on q, k (in place)
    rope_kernel<<<(ROWS * DD / 2) / 256, 256>>>(q);
    rope_kernel<<<(ROWS * DD / 2) / 256, 256>>>(k);
    // 4) attention
    attn_kernel<<<dim3(TT / QB, NH, BB), 256>>>(q, k, v, mask, att);
    // 5) x2 = x + att @ Wo^T + bo
    gemm_mma<<<gD, 256>>>(att, Wo, bo, x, x2, DD, DD, 0);
    // 6) h = LN(x2)
    ln_kernel<<<ROWS, 256>>>(x2, g2, be2, h);
    // 7) ff = gelu(h @ W1^T + b1)
    gemm_mma<<<gDF, 256>>>(h, W1, b1, nullptr, ff, DFF, DD, 1);
    // 8) out = x2 + ff @ W2^T + b2
    gemm_mma<<<gD, 256>>>(ff, W2, b2, x2, out, DD, DFF, 0);
}

// round 6
// speedup vs baseline: 2.7929x; 2.2346x over previous
#include <cuda_runtime.h>
#include <cuda_bf16.h>
#include <math.h>
#include <stddef.h>
#include <stdint.h>

// Problem constants
#define BB    4
#define TT    2048
#define DD    1024
#define NH    16
#define DKH   64
#define DFF   4096
#define ROWS  (BB*TT)          // 8192

// ---------------- scratch (static device globals; no allocation allowed) ----
__device__ float g_h  [ (size_t)ROWS * DD ];
__device__ float g_q  [ (size_t)ROWS * DD ];
__device__ float g_k  [ (size_t)ROWS * DD ];
__device__ float g_v  [ (size_t)ROWS * DD ];
__device__ float g_att[ (size_t)ROWS * DD ];
__device__ float g_x2 [ (size_t)ROWS * DD ];
__device__ float g_ff [ (size_t)ROWS * DFF ];

__device__ __forceinline__ void mma16816(float* c, const uint32_t* a, const uint32_t* b) {
    asm volatile(
        "mma.sync.aligned.m16n8k16.row.col.f32.bf16.bf16.f32 "
        "{%0,%1,%2,%3}, {%4,%5,%6,%7}, {%8,%9}, {%0,%1,%2,%3};"
        : "+f"(c[0]), "+f"(c[1]), "+f"(c[2]), "+f"(c[3])
        : "r"(a[0]), "r"(a[1]), "r"(a[2]), "r"(a[3]), "r"(b[0]), "r"(b[1]));
}

__device__ __forceinline__ uint32_t pack_hi(float x, float y,
                                            __nv_bfloat16& hx, __nv_bfloat16& hy) {
    hx = __float2bfloat16(x); hy = __float2bfloat16(y);
    __nv_bfloat162 p = {hx, hy};
    return *(uint32_t*)&p;
}
__device__ __forceinline__ uint32_t pack_bf(float x, float y) {
    __nv_bfloat162 p = { __float2bfloat16(x), __float2bfloat16(y) };
    return *(uint32_t*)&p;
}

// ==================== warp-level bf16 MMA GEMM (unchanged from R5) ==========
#define BM 128
#define BN 128
#define BK 32
#define LDS_PAD 40

__global__ __launch_bounds__(256)
void gemm_mma(const float* __restrict__ A, const float* __restrict__ B,
              const float* __restrict__ bias, const float* __restrict__ R,
              float* __restrict__ C, int Nc, int K, int gelu)
{
    __shared__ __nv_bfloat16 Ah[BM][LDS_PAD];
    __shared__ __nv_bfloat16 Al[BM][LDS_PAD];
    __shared__ __nv_bfloat16 Bh[BN][LDS_PAD];
    __shared__ __nv_bfloat16 Bl[BN][LDS_PAD];

    const int tid  = threadIdx.x;
    const int wid  = tid >> 5;
    const int lane = tid & 31;
    const int g    = lane >> 2;
    const int tg   = lane & 3;
    const int wm0  = (wid & 3) * 32;
    const int wn0  = (wid >> 2) * 64;
    const int bm   = blockIdx.y * BM;
    const int bn   = blockIdx.x * BN;

    const int lrow = tid >> 1;
    const int lcol = (tid & 1) * 16;
    const float* Ald = A + (size_t)(bm + lrow) * K + lcol;
    const float* Bld = B + (size_t)(bn + lrow) * K + lcol;

    float acc[2][8][4] = {};
    const int NIT = K / BK;

    float4 apre[4], bpre[4];
    #pragma unroll
    for (int i = 0; i < 4; i++) { apre[i] = *(const float4*)(Ald + i * 4);
                                  bpre[i] = *(const float4*)(Bld + i * 4); }

    for (int iter = 0; iter < NIT; iter++) {
        __syncthreads();
        #pragma unroll
        for (int i = 0; i < 4; i++) {
            float4 av = apre[i], bv = bpre[i];
            __nv_bfloat16 h0, h1, h2, h3;
            uint32_t u01 = pack_hi(av.x, av.y, h0, h1);
            uint32_t u23 = pack_hi(av.z, av.w, h2, h3);
            *(uint32_t*)&Ah[lrow][lcol + i*4]     = u01;
            *(uint32_t*)&Ah[lrow][lcol + i*4 + 2] = u23;
            *(uint32_t*)&Al[lrow][lcol + i*4]     =
                pack_bf(av.x - __bfloat162float(h0), av.y - __bfloat162float(h1));
            *(uint32_t*)&Al[lrow][lcol + i*4 + 2] =
                pack_bf(av.z - __bfloat162float(h2), av.w - __bfloat162float(h3));

            u01 = pack_hi(bv.x, bv.y, h0, h1);
            u23 = pack_hi(bv.z, bv.w, h2, h3);
            *(uint32_t*)&Bh[lrow][lcol + i*4]     = u01;
            *(uint32_t*)&Bh[lrow][lcol + i*4 + 2] = u23;
            *(uint32_t*)&Bl[lrow][lcol + i*4]     =
                pack_bf(bv.x - __bfloat162float(h0), bv.y - __bfloat162float(h1));
            *(uint32_t*)&Bl[lrow][lcol + i*4 + 2] =
                pack_bf(bv.z - __bfloat162float(h2), bv.w - __bfloat162float(h3));
        }
        __syncthreads();

        if (iter + 1 < NIT) {
            const float* An = Ald + (iter + 1) * BK;
            const float* Bn = Bld + (iter + 1) * BK;
            #pragma unroll
            for (int i = 0; i < 4; i++) { apre[i] = *(const float4*)(An + i * 4);
                                          bpre[i] = *(const float4*)(Bn + i * 4); }
        }

        #pragma unroll
        for (int k0 = 0; k0 < BK; k0 += 16) {
            uint32_t afh[2][4], afl[2][4];
            #pragma unroll
            for (int mi = 0; mi < 2; mi++) {
                const int r0 = wm0 + mi * 16 + g;
                const int c0 = k0 + tg * 2;
                afh[mi][0] = *(const uint32_t*)&Ah[r0    ][c0    ];
                afh[mi][1] = *(const uint32_t*)&Ah[r0 + 8][c0    ];
                afh[mi][2] = *(const uint32_t*)&Ah[r0    ][c0 + 8];
                afh[mi][3] = *(const uint32_t*)&Ah[r0 + 8][c0 + 8];
                afl[mi][0] = *(const uint32_t*)&Al[r0    ][c0    ];
                afl[mi][1] = *(const uint32_t*)&Al[r0 + 8][c0    ];
                afl[mi][2] = *(const uint32_t*)&Al[r0    ][c0 + 8];
                afl[mi][3] = *(const uint32_t*)&Al[r0 + 8][c0 + 8];
            }
            #pragma unroll
            for (int ni = 0; ni < 8; ni++) {
                const int nr = wn0 + ni * 8 + g;
                const int kc = k0 + tg * 2;
                uint32_t bfh[2], bfl[2];
                bfh[0] = *(const uint32_t*)&Bh[nr][kc    ];
                bfh[1] = *(const uint32_t*)&Bh[nr][kc + 8];
                bfl[0] = *(const uint32_t*)&Bl[nr][kc    ];
                bfl[1] = *(const uint32_t*)&Bl[nr][kc + 8];
                #pragma unroll
                for (int mi = 0; mi < 2; mi++) {
                    mma16816(acc[mi][ni], afh[mi], bfh);
                    mma16816(acc[mi][ni], afh[mi], bfl);
                    mma16816(acc[mi][ni], afl[mi], bfh);
                }
            }
        }
    }

    #pragma unroll
    for (int mi = 0; mi < 2; mi++) {
        #pragma unroll
        for (int ni = 0; ni < 8; ni++) {
            const int n  = bn + wn0 + ni * 8 + tg * 2;
            const float bs0 = __ldg(bias + n), bs1 = __ldg(bias + n + 1);
            #pragma unroll
            for (int half = 0; half < 2; half++) {
                const int m = bm + wm0 + mi * 16 + g + half * 8;
                float v0 = acc[mi][ni][half * 2]     + bs0;
                float v1 = acc[mi][ni][half * 2 + 1] + bs1;
                if (R) {
                    const float* Rp = R + (size_t)m * Nc + n;
                    v0 += Rp[0]; v1 += Rp[1];
                }
                if (gelu) {
                    v0 = 0.5f * v0 * (1.0f + erff(v0 * 0.70710678118654752f));
                    v1 = 0.5f * v1 * (1.0f + erff(v1 * 0.70710678118654752f));
                }
                float2 o = { v0, v1 };
                *(float2*)(C + (size_t)m * Nc + n) = o;
            }
        }
    }
}

// ==================== MMA flash attention ===================================
// One block = 128 threads (4 warps) per (b, h, 64-query tile).
// Warp w owns 16 query rows. Online softmax in fragment registers.
#define AS 64          // keys per tile
#define APAD 72        // smem row stride (bf16)

__global__ __launch_bounds__(128)
void attn_mma(const float* __restrict__ Q, const float* __restrict__ K,
              const float* __restrict__ V, const unsigned char* __restrict__ mask,
              float* __restrict__ O)
{
    __shared__ __nv_bfloat16 Ks[AS][APAD];   // [s][d]
    __shared__ __nv_bfloat16 Vt[DKH][APAD];  // [d][s]
    __shared__ unsigned char Ms[AS];

    const int tid  = threadIdx.x;
    const int wid  = tid >> 5;
    const int lane = tid & 31;
    const int g    = lane >> 2;
    const int tg   = lane & 3;
    const int qt   = blockIdx.x;
    const int hh   = blockIdx.y;
    const int bb   = blockIdx.z;
    const int q0   = qt * 64;
    const size_t base = ((size_t)bb * TT) * DD + (size_t)hh * DKH;

    // Q fragments in registers (scaled by 1/8), rows r0 = q0+wid*16+g, r1 = +8
    const int qr0 = q0 + wid * 16 + g;
    uint32_t qa[4][4];
    {
        const float* Qr0 = Q + base + (size_t)qr0 * DD;
        const float* Qr1 = Qr0 + 8 * DD;
        #pragma unroll
        for (int kt = 0; kt < 4; kt++) {
            const int c = kt * 16 + tg * 2;
            float2 x0 = *(const float2*)(Qr0 + c);
            float2 x1 = *(const float2*)(Qr1 + c);
            float2 x2 = *(const float2*)(Qr0 + c + 8);
            float2 x3 = *(const float2*)(Qr1 + c + 8);
            qa[kt][0] = pack_bf(x0.x * 0.125f, x0.y * 0.125f);
            qa[kt][1] = pack_bf(x1.x * 0.125f, x1.y * 0.125f);
            qa[kt][2] = pack_bf(x2.x * 0.125f, x2.y * 0.125f);
            qa[kt][3] = pack_bf(x3.x * 0.125f, x3.y * 0.125f);
        }
    }

    float m0 = -INFINITY, m1 = -INFINITY, l0 = 0.f, l1 = 0.f;
    float oacc[8][4] = {};

    // loader mapping: thread t -> key row t>>1, 32 dims starting (t&1)*32
    const int lrow = tid >> 1;
    const int lcol = (tid & 1) * 32;

    for (int s0 = 0; s0 < TT; s0 += AS) {
        __syncthreads();
        {
            const float* Kr = K + base + (size_t)(s0 + lrow) * DD + lcol;
            const float* Vr = V + base + (size_t)(s0 + lrow) * DD + lcol;
            #pragma unroll
            for (int i = 0; i < 8; i++) {
                float4 kv = *(const float4*)(Kr + i * 4);
                *(uint32_t*)&Ks[lrow][lcol + i*4]     = pack_bf(kv.x, kv.y);
                *(uint32_t*)&Ks[lrow][lcol + i*4 + 2] = pack_bf(kv.z, kv.w);
                float4 vv = *(const float4*)(Vr + i * 4);
                Vt[lcol + i*4    ][lrow] = __float2bfloat16(vv.x);
                Vt[lcol + i*4 + 1][lrow] = __float2bfloat16(vv.y);
                Vt[lcol + i*4 + 2][lrow] = __float2bfloat16(vv.z);
                Vt[lcol + i*4 + 3][lrow] = __float2bfloat16(vv.w);
            }
            if (tid < AS) Ms[tid] = mask[(size_t)bb * TT + s0 + tid];
        }
        __syncthreads();

        // S = Qf @ K^T : c[ni][*] covers key cols ni*8 + tg*2(+1)
        float c[8][4] = {};
        #pragma unroll
        for (int ni = 0; ni < 8; ni++) {
            const int nr = ni * 8 + g;
            #pragma unroll
            for (int kt = 0; kt < 4; kt++) {
                const int kc = kt * 16 + tg * 2;
                uint32_t bf[2];
                bf[0] = *(const uint32_t*)&Ks[nr][kc];
                bf[1] = *(const uint32_t*)&Ks[nr][kc + 8];
                mma16816(c[ni], qa[kt], bf);
            }
        }

        // mask + row max
        float mt0 = -INFINITY, mt1 = -INFINITY;
        #pragma unroll
        for (int ni = 0; ni < 8; ni++) {
            const int sc0 = ni * 8 + tg * 2;
            if (Ms[sc0])     { c[ni][0] = -INFINITY; c[ni][2] = -INFINITY; }
            if (Ms[sc0 + 1]) { c[ni][1] = -INFINITY; c[ni][3] = -INFINITY; }
            mt0 = fmaxf(mt0, fmaxf(c[ni][0], c[ni][1]));
            mt1 = fmaxf(mt1, fmaxf(c[ni][2], c[ni][3]));
        }
        mt0 = fmaxf(mt0, __shfl_xor_sync(0xffffffffu, mt0, 1));
        mt0 = fmaxf(mt0, __shfl_xor_sync(0xffffffffu, mt0, 2));
        mt1 = fmaxf(mt1, __shfl_xor_sync(0xffffffffu, mt1, 1));
        mt1 = fmaxf(mt1, __shfl_xor_sync(0xffffffffu, mt1, 2));

        const float mn0 = fmaxf(m0, mt0);
        const float mn1 = fmaxf(m1, mt1);
        const float al0 = __expf(m0 - mn0);
        const float al1 = __expf(m1 - mn1);
        m0 = mn0; m1 = mn1;

        // exponentiate in place, accumulate partial row sums
        float ps0 = 0.f, ps1 = 0.f;
        #pragma unroll
        for (int ni = 0; ni < 8; ni++) {
            c[ni][0] = __expf(c[ni][0] - mn0);
            c[ni][1] = __expf(c[ni][1] - mn0);
            c[ni][2] = __expf(c[ni][2] - mn1);
            c[ni][3] = __expf(c[ni][3] - mn1);
            ps0 += c[ni][0] + c[ni][1];
            ps1 += c[ni][2] + c[ni][3];
        }
        ps0 += __shfl_xor_sync(0xffffffffu, ps0, 1);
        ps0 += __shfl_xor_sync(0xffffffffu, ps0, 2);
        ps1 += __shfl_xor_sync(0xffffffffu, ps1, 1);
        ps1 += __shfl_xor_sync(0xffffffffu, ps1, 2);
        l0 = l0 * al0 + ps0;
        l1 = l1 * al1 + ps1;

        #pragma unroll
        for (int di = 0; di < 8; di++) {
            oacc[di][0] *= al0; oacc[di][1] *= al0;
            oacc[di][2] *= al1; oacc[di][3] *= al1;
        }

        // P fragments map directly from S C-fragments; P @ V
        #pragma unroll
        for (int st = 0; st < 4; st++) {
            uint32_t pa[4];
            pa[0] = pack_bf(c[2*st][0],   c[2*st][1]);
            pa[1] = pack_bf(c[2*st][2],   c[2*st][3]);
            pa[2] = pack_bf(c[2*st+1][0], c[2*st+1][1]);
            pa[3] = pack_bf(c[2*st+1][2], c[2*st+1][3]);
            #pragma unroll
            for (int di = 0; di < 8; di++) {
                const int nr = di * 8 + g;
                const int kc = st * 16 + tg * 2;
                uint32_t bf[2];
                bf[0] = *(const uint32_t*)&Vt[nr][kc];
                bf[1] = *(const uint32_t*)&Vt[nr][kc + 8];
                mma16816(oacc[di], pa, bf);
            }
        }
    }

    const float inv0 = 1.0f / l0;
    const float inv1 = 1.0f / l1;
    float* O0 = O + base + (size_t)qr0 * DD;
    float* O1 = O0 + 8 * DD;
    #pragma unroll
    for (int di = 0; di < 8; di++) {
        const int d = di * 8 + tg * 2;
        float2 a = { oacc[di][0] * inv0, oacc[di][1] * inv0 };
        float2 b = { oacc[di][2] * inv1, oacc[di][3] * inv1 };
        *(float2*)(O0 + d) = a;
        *(float2*)(O1 + d) = b;
    }
}

// ---------------- block reduction helper ------------------------------------
__device__ __forceinline__ float block_sum256(float v) {
    __shared__ float red[8];
    #pragma unroll
    for (int off = 16; off; off >>= 1)
        v += __shfl_xor_sync(0xffffffffu, v, off);
    if ((threadIdx.x & 31) == 0) red[threadIdx.x >> 5] = v;
    __syncthreads();
    if (threadIdx.x < 32) {
        float t = (threadIdx.x < 8) ? red[threadIdx.x] : 0.0f;
        #pragma unroll
        for (int off = 4; off; off >>= 1)
            t += __shfl_xor_sync(0xffffffffu, t, off);
        if (threadIdx.x == 0) red[0] = t;
    }
    __syncthreads();
    float r = red[0];
    __syncthreads();
    return r;
}

// ---------------- LayerNorm --------------------------------------------------
__global__ __launch_bounds__(256)
void ln_kernel(const float* __restrict__ x, const float* __restrict__ g,
               const float* __restrict__ b, float* __restrict__ o)
{
    const int row = blockIdx.x;
    const int tid = threadIdx.x;
    const float* xr = x + (size_t)row * DD;
    float4 v = *(const float4*)(xr + tid * 4);

    float s = v.x + v.y + v.z + v.w;
    float mean = block_sum256(s) * (1.0f / DD);

    float dx = v.x - mean, dy = v.y - mean, dz = v.z - mean, dw = v.w - mean;
    float ss = dx*dx + dy*dy + dz*dz + dw*dw;
    float var = block_sum256(ss) * (1.0f / DD);
    float rstd = rsqrtf(var + 1e-5f);

    float4 gv = *(const float4*)(g + tid * 4);
    float4 bv = *(const float4*)(b + tid * 4);
    float4 ov;
    ov.x = dx * rstd * gv.x + bv.x;
    ov.y = dy * rstd * gv.y + bv.y;
    ov.z = dz * rstd * gv.z + bv.z;
    ov.w = dw * rstd * gv.w + bv.w;
    *(float4*)(o + (size_t)row * DD + tid * 4) = ov;
}

// ---------------- RoPE -------------------------------------------------------
__global__ __launch_bounds__(256)
void rope_kernel(float* __restrict__ x)
{
    const int idx  = blockIdx.x * blockDim.x + threadIdx.x;
    const int pair = idx & 511;
    const int row  = idx >> 9;
    const int t    = row & (TT - 1);
    const int i    = pair & 31;
    const float ang = (float)t * expf(-0.28782313662425537f * (float)i);
    float s, c;
    sincosf(ang, &s, &c);
    float2* p = (float2*)(x + ((size_t)row << 10) + (pair << 1));
    float2 v = *p;
    float2 o;
    o.x = v.x * c - v.y * s;
    o.y = v.x * s + v.y * c;
    *p = o;
}

// ---------------- launch ----------------------------------------------------
extern "C" void kernel_launch(void* const* d_in, const int* in_sizes, int n_in,
                              void* d_out, int out_size)
{
    const float* x   = (const float*)d_in[0];
    const unsigned char* mask = (const unsigned char*)d_in[1];
    const float* Wq  = (const float*)d_in[2];
    const float* bq  = (const float*)d_in[3];
    const float* Wk  = (const float*)d_in[4];
    const float* bk  = (const float*)d_in[5];
    const float* Wv  = (const float*)d_in[6];
    const float* bv  = (const float*)d_in[7];
    const float* Wo  = (const float*)d_in[8];
    const float* bo  = (const float*)d_in[9];
    const float* W1  = (const float*)d_in[10];
    const float* b1  = (const float*)d_in[11];
    const float* W2  = (const float*)d_in[12];
    const float* b2  = (const float*)d_in[13];
    const float* g1  = (const float*)d_in[14];
    const float* be1 = (const float*)d_in[15];
    const float* g2  = (const float*)d_in[16];
    const float* be2 = (const float*)d_in[17];
    float* out = (float*)d_out;

    float *h, *q, *k, *v, *att, *x2, *ff;
    cudaGetSymbolAddress((void**)&h,   g_h);
    cudaGetSymbolAddress((void**)&q,   g_q);
    cudaGetSymbolAddress((void**)&k,   g_k);
    cudaGetSymbolAddress((void**)&v,   g_v);
    cudaGetSymbolAddress((void**)&att, g_att);
    cudaGetSymbolAddress((void**)&x2,  g_x2);
    cudaGetSymbolAddress((void**)&ff,  g_ff);

    const dim3 gD (DD  / BN, ROWS / BM);   // (8,64)
    const dim3 gDF(DFF / BN, ROWS / BM);   // (32,64)

    // 1) h = LN(x)
    ln_kernel<<<ROWS, 256>>>(x, g1, be1, h);
    // 2) q,k,v projections
    gemm_mma<<<gD, 256>>>(h, Wq, bq, nullptr, q, DD, DD, 0);
    gemm_mma<<<gD, 256>>>(h, Wk, bk, nullptr, k, DD, DD, 0);
    gemm_mma<<<gD, 256>>>(h, Wv, bv, nullptr, v, DD, DD, 0);
    // 3) rope on q, k (in place)
    rope_kernel<<<(ROWS * DD / 2) / 256, 256>>>(q);
    rope_kernel<<<(ROWS * DD / 2) / 256, 256>>>(k);
    // 4) attention (tensor-core flash)
    attn_mma<<<dim3(TT / 64, NH, BB), 128>>>(q, k, v, mask, att);
    // 5) x2 = x + att @ Wo^T + bo
    gemm_mma<<<gD, 256>>>(att, Wo, bo, x, x2, DD, DD, 0);
    // 6) h = LN(x2)
    ln_kernel<<<ROWS, 256>>>(x2, g2, be2, h);
    // 7) ff = gelu(h @ W1^T + b1)
    gemm_mma<<<gDF, 256>>>(h, W1, b1, nullptr, ff, DFF, DD, 1);
    // 8) out = x2 + ff @ W2^T + b2
    gemm_mma<<<gD, 256>>>(ff, W2, b2, x2, out, DD, DFF, 0);
}

// round 7
// speedup vs baseline: 2.8117x; 1.0067x over previous
#include <cuda_runtime.h>
#include <cuda_bf16.h>
#include <math.h>
#include <stddef.h>
#include <stdint.h>

// Problem constants
#define BB    4
#define TT    2048
#define DD    1024
#define NH    16
#define DKH   64
#define DFF   4096
#define ROWS  (BB*TT)          // 8192

// ---------------- scratch (static device globals; no allocation allowed) ----
__device__ float g_h  [ (size_t)ROWS * DD ];
__device__ float g_q  [ (size_t)ROWS * DD ];
__device__ float g_k  [ (size_t)ROWS * DD ];
__device__ float g_v  [ (size_t)ROWS * DD ];
__device__ float g_x2 [ (size_t)ROWS * DD ];

__device__ __nv_bfloat16 g_hH  [ (size_t)ROWS * DD ];
__device__ __nv_bfloat16 g_hL  [ (size_t)ROWS * DD ];
__device__ __nv_bfloat16 g_attH[ (size_t)ROWS * DD ];
__device__ __nv_bfloat16 g_attL[ (size_t)ROWS * DD ];
__device__ __nv_bfloat16 g_ffH [ (size_t)ROWS * DFF ];
__device__ __nv_bfloat16 g_ffL [ (size_t)ROWS * DFF ];
__device__ __nv_bfloat16 g_WqH [ (size_t)DD * DD ];
__device__ __nv_bfloat16 g_WqL [ (size_t)DD * DD ];
__device__ __nv_bfloat16 g_WkH [ (size_t)DD * DD ];
__device__ __nv_bfloat16 g_WkL [ (size_t)DD * DD ];
__device__ __nv_bfloat16 g_WvH [ (size_t)DD * DD ];
__device__ __nv_bfloat16 g_WvL [ (size_t)DD * DD ];
__device__ __nv_bfloat16 g_WoH [ (size_t)DD * DD ];
__device__ __nv_bfloat16 g_WoL [ (size_t)DD * DD ];
__device__ __nv_bfloat16 g_W1H [ (size_t)DFF * DD ];
__device__ __nv_bfloat16 g_W1L [ (size_t)DFF * DD ];
__device__ __nv_bfloat16 g_W2H [ (size_t)DD * DFF ];
__device__ __nv_bfloat16 g_W2L [ (size_t)DD * DFF ];

__device__ __forceinline__ void mma16816(float* c, const uint32_t* a, const uint32_t* b) {
    asm volatile(
        "mma.sync.aligned.m16n8k16.row.col.f32.bf16.bf16.f32 "
        "{%0,%1,%2,%3}, {%4,%5,%6,%7}, {%8,%9}, {%0,%1,%2,%3};"
        : "+f"(c[0]), "+f"(c[1]), "+f"(c[2]), "+f"(c[3])
        : "r"(a[0]), "r"(a[1]), "r"(a[2]), "r"(a[3]), "r"(b[0]), "r"(b[1]));
}

__device__ __forceinline__ uint32_t pack_bf(float x, float y) {
    __nv_bfloat162 p = { __float2bfloat16(x), __float2bfloat16(y) };
    return *(uint32_t*)&p;
}
// split x,y into hi (returned) and lo (written)
__device__ __forceinline__ uint32_t split_bf(float x, float y, uint32_t& lo) {
    __nv_bfloat16 hx = __float2bfloat16(x), hy = __float2bfloat16(y);
    __nv_bfloat162 h = { hx, hy };
    __nv_bfloat162 l = { __float2bfloat16(x - __bfloat162float(hx)),
                         __float2bfloat16(y - __bfloat162float(hy)) };
    lo = *(uint32_t*)&l;
    return *(uint32_t*)&h;
}

// ---------------- weight split conversion -----------------------------------
__global__ __launch_bounds__(256)
void convert_split(const float* __restrict__ src, __nv_bfloat16* __restrict__ H,
                   __nv_bfloat16* __restrict__ L)
{
    const int i = blockIdx.x * 256 + threadIdx.x;   // over float4s
    float4 v = ((const float4*)src)[i];
    uint32_t l0, l1;
    uint32_t h0 = split_bf(v.x, v.y, l0);
    uint32_t h1 = split_bf(v.z, v.w, l1);
    uint2 hh = { h0, h1 }, ll = { l0, l1 };
    *(uint2*)(H + (size_t)i * 4) = hh;
    *(uint2*)(L + (size_t)i * 4) = ll;
}

// ==================== bf16 MMA GEMM (pre-split operands) ====================
// C[M,N] = (AH+AL)[M,K] @ (BH+BL)[N,K]^T + bias (+res)(+gelu)
// acc = AhBh + AhBl + AlBh. Block 128x128, BK=32, 8 warps, warp tile 32x64.
#define BM 128
#define BN 128
#define BK 32
#define LDS_PAD 40

__global__ __launch_bounds__(256)
void gemm_bf(const __nv_bfloat16* __restrict__ AH, const __nv_bfloat16* __restrict__ AL,
             const __nv_bfloat16* __restrict__ BH, const __nv_bfloat16* __restrict__ BL,
             const float* __restrict__ bias, const float* __restrict__ R,
             float* __restrict__ C, __nv_bfloat16* __restrict__ CH,
             __nv_bfloat16* __restrict__ CL, int Nc, int K, int gelu)
{
    __shared__ __nv_bfloat16 Ah[BM][LDS_PAD];
    __shared__ __nv_bfloat16 Al[BM][LDS_PAD];
    __shared__ __nv_bfloat16 Bh[BN][LDS_PAD];
    __shared__ __nv_bfloat16 Bl[BN][LDS_PAD];

    const int tid  = threadIdx.x;
    const int wid  = tid >> 5;
    const int lane = tid & 31;
    const int g    = lane >> 2;
    const int tg   = lane & 3;
    const int wm0  = (wid & 3) * 32;
    const int wn0  = (wid >> 2) * 64;
    const int bm   = blockIdx.y * BM;
    const int bn   = blockIdx.x * BN;

    // loader: thread t -> row t>>1, 16 bf16 starting (t&1)*16
    const int lrow = tid >> 1;
    const int lcol = (tid & 1) * 16;
    const size_t aoff = (size_t)(bm + lrow) * K + lcol;
    const size_t boff = (size_t)(bn + lrow) * K + lcol;

    float acc[2][8][4] = {};
    const int NIT = K / BK;

    uint4 pre[8];
    pre[0] = *(const uint4*)(AH + aoff);     pre[1] = *(const uint4*)(AH + aoff + 8);
    pre[2] = *(const uint4*)(AL + aoff);     pre[3] = *(const uint4*)(AL + aoff + 8);
    pre[4] = *(const uint4*)(BH + boff);     pre[5] = *(const uint4*)(BH + boff + 8);
    pre[6] = *(const uint4*)(BL + boff);     pre[7] = *(const uint4*)(BL + boff + 8);

    for (int iter = 0; iter < NIT; iter++) {
        __syncthreads();   // previous compute reads done
        *(uint4*)&Ah[lrow][lcol]     = pre[0];
        *(uint4*)&Ah[lrow][lcol + 8] = pre[1];
        *(uint4*)&Al[lrow][lcol]     = pre[2];
        *(uint4*)&Al[lrow][lcol + 8] = pre[3];
        *(uint4*)&Bh[lrow][lcol]     = pre[4];
        *(uint4*)&Bh[lrow][lcol + 8] = pre[5];
        *(uint4*)&Bl[lrow][lcol]     = pre[6];
        *(uint4*)&Bl[lrow][lcol + 8] = pre[7];
        __syncthreads();

        if (iter + 1 < NIT) {
            const size_t an = aoff + (size_t)(iter + 1) * BK;
            const size_t bo = boff + (size_t)(iter + 1) * BK;
            pre[0] = *(const uint4*)(AH + an);     pre[1] = *(const uint4*)(AH + an + 8);
            pre[2] = *(const uint4*)(AL + an);     pre[3] = *(const uint4*)(AL + an + 8);
            pre[4] = *(const uint4*)(BH + bo);     pre[5] = *(const uint4*)(BH + bo + 8);
            pre[6] = *(const uint4*)(BL + bo);     pre[7] = *(const uint4*)(BL + bo + 8);
        }

        #pragma unroll
        for (int k0 = 0; k0 < BK; k0 += 16) {
            uint32_t afh[2][4], afl[2][4];
            #pragma unroll
            for (int mi = 0; mi < 2; mi++) {
                const int r0 = wm0 + mi * 16 + g;
                const int c0 = k0 + tg * 2;
                afh[mi][0] = *(const uint32_t*)&Ah[r0    ][c0    ];
                afh[mi][1] = *(const uint32_t*)&Ah[r0 + 8][c0    ];
                afh[mi][2] = *(const uint32_t*)&Ah[r0    ][c0 + 8];
                afh[mi][3] = *(const uint32_t*)&Ah[r0 + 8][c0 + 8];
                afl[mi][0] = *(const uint32_t*)&Al[r0    ][c0    ];
                afl[mi][1] = *(const uint32_t*)&Al[r0 + 8][c0    ];
                afl[mi][2] = *(const uint32_t*)&Al[r0    ][c0 + 8];
                afl[mi][3] = *(const uint32_t*)&Al[r0 + 8][c0 + 8];
            }
            #pragma unroll
            for (int ni = 0; ni < 8; ni++) {
                const int nr = wn0 + ni * 8 + g;
                const int kc = k0 + tg * 2;
                uint32_t bfh[2], bfl[2];
                bfh[0] = *(const uint32_t*)&Bh[nr][kc    ];
                bfh[1] = *(const uint32_t*)&Bh[nr][kc + 8];
                bfl[0] = *(const uint32_t*)&Bl[nr][kc    ];
                bfl[1] = *(const uint32_t*)&Bl[nr][kc + 8];
                #pragma unroll
                for (int mi = 0; mi < 2; mi++) {
                    mma16816(acc[mi][ni], afh[mi], bfh);
                    mma16816(acc[mi][ni], afh[mi], bfl);
                    mma16816(acc[mi][ni], afl[mi], bfh);
                }
            }
        }
    }

    // epilogue
    #pragma unroll
    for (int mi = 0; mi < 2; mi++) {
        #pragma unroll
        for (int ni = 0; ni < 8; ni++) {
            const int n  = bn + wn0 + ni * 8 + tg * 2;
            const float bs0 = __ldg(bias + n), bs1 = __ldg(bias + n + 1);
            #pragma unroll
            for (int half = 0; half < 2; half++) {
                const int m = bm + wm0 + mi * 16 + g + half * 8;
                float v0 = acc[mi][ni][half * 2]     + bs0;
                float v1 = acc[mi][ni][half * 2 + 1] + bs1;
                if (R) {
                    const float* Rp = R + (size_t)m * Nc + n;
                    v0 += Rp[0]; v1 += Rp[1];
                }
                if (gelu) {
                    v0 = 0.5f * v0 * (1.0f + erff(v0 * 0.70710678118654752f));
                    v1 = 0.5f * v1 * (1.0f + erff(v1 * 0.70710678118654752f));
                }
                if (C) {
                    float2 o = { v0, v1 };
                    *(float2*)(C + (size_t)m * Nc + n) = o;
                }
                if (CH) {
                    uint32_t lo;
                    uint32_t hi = split_bf(v0, v1, lo);
                    *(uint32_t*)(CH + (size_t)m * Nc + n) = hi;
                    *(uint32_t*)(CL + (size_t)m * Nc + n) = lo;
                }
            }
        }
    }
}

// ==================== MMA flash attention ===================================
// One block = 128 threads (4 warps) per (b, h, 64-query tile).
// Epilogue writes bf16 hi/lo split of the output (consumed by Wo GEMM).
#define AS 64
#define APAD 72

__global__ __launch_bounds__(128)
void attn_mma(const float* __restrict__ Q, const float* __restrict__ K,
              const float* __restrict__ V, const unsigned char* __restrict__ mask,
              __nv_bfloat16* __restrict__ OH, __nv_bfloat16* __restrict__ OL)
{
    __shared__ __nv_bfloat16 Ks[AS][APAD];   // [s][d]
    __shared__ __nv_bfloat16 Vt[DKH][APAD];  // [d][s]
    __shared__ unsigned char Ms[AS];

    const int tid  = threadIdx.x;
    const int wid  = tid >> 5;
    const int lane = tid & 31;
    const int g    = lane >> 2;
    const int tg   = lane & 3;
    const int qt   = blockIdx.x;
    const int hh   = blockIdx.y;
    const int bb   = blockIdx.z;
    const int q0   = qt * 64;
    const size_t base = ((size_t)bb * TT) * DD + (size_t)hh * DKH;

    const int qr0 = q0 + wid * 16 + g;
    uint32_t qa[4][4];
    {
        const float* Qr0 = Q + base + (size_t)qr0 * DD;
        const float* Qr1 = Qr0 + 8 * DD;
        #pragma unroll
        for (int kt = 0; kt < 4; kt++) {
            const int c = kt * 16 + tg * 2;
            float2 x0 = *(const float2*)(Qr0 + c);
            float2 x1 = *(const float2*)(Qr1 + c);
            float2 x2 = *(const float2*)(Qr0 + c + 8);
            float2 x3 = *(const float2*)(Qr1 + c + 8);
            qa[kt][0] = pack_bf(x0.x * 0.125f, x0.y * 0.125f);
            qa[kt][1] = pack_bf(x1.x * 0.125f, x1.y * 0.125f);
            qa[kt][2] = pack_bf(x2.x * 0.125f, x2.y * 0.125f);
            qa[kt][3] = pack_bf(x3.x * 0.125f, x3.y * 0.125f);
        }
    }

    float m0 = -INFINITY, m1 = -INFINITY, l0 = 0.f, l1 = 0.f;
    float oacc[8][4] = {};

    const int lrow = tid >> 1;
    const int lcol = (tid & 1) * 32;

    for (int s0 = 0; s0 < TT; s0 += AS) {
        __syncthreads();
        {
            const float* Kr = K + base + (size_t)(s0 + lrow) * DD + lcol;
            const float* Vr = V + base + (size_t)(s0 + lrow) * DD + lcol;
            #pragma unroll
            for (int i = 0; i < 8; i++) {
                float4 kv = *(const float4*)(Kr + i * 4);
                *(uint32_t*)&Ks[lrow][lcol + i*4]     = pack_bf(kv.x, kv.y);
                *(uint32_t*)&Ks[lrow][lcol + i*4 + 2] = pack_bf(kv.z, kv.w);
                float4 vv = *(const float4*)(Vr + i * 4);
                Vt[lcol + i*4    ][lrow] = __float2bfloat16(vv.x);
                Vt[lcol + i*4 + 1][lrow] = __float2bfloat16(vv.y);
                Vt[lcol + i*4 + 2][lrow] = __float2bfloat16(vv.z);
                Vt[lcol + i*4 + 3][lrow] = __float2bfloat16(vv.w);
            }
            if (tid < AS) Ms[tid] = mask[(size_t)bb * TT + s0 + tid];
        }
        __syncthreads();

        float c[8][4] = {};
        #pragma unroll
        for (int ni = 0; ni < 8; ni++) {
            const int nr = ni * 8 + g;
            #pragma unroll
            for (int kt = 0; kt < 4; kt++) {
                const int kc = kt * 16 + tg * 2;
                uint32_t bf[2];
                bf[0] = *(const uint32_t*)&Ks[nr][kc];
                bf[1] = *(const uint32_t*)&Ks[nr][kc + 8];
                mma16816(c[ni], qa[kt], bf);
            }
        }

        float mt0 = -INFINITY, mt1 = -INFINITY;
        #pragma unroll
        for (int ni = 0; ni < 8; ni++) {
            const int sc0 = ni * 8 + tg * 2;
            if (Ms[sc0])     { c[ni][0] = -INFINITY; c[ni][2] = -INFINITY; }
            if (Ms[sc0 + 1]) { c[ni][1] = -INFINITY; c[ni][3] = -INFINITY; }
            mt0 = fmaxf(mt0, fmaxf(c[ni][0], c[ni][1]));
            mt1 = fmaxf(mt1, fmaxf(c[ni][2], c[ni][3]));
        }
        mt0 = fmaxf(mt0, __shfl_xor_sync(0xffffffffu, mt0, 1));
        mt0 = fmaxf(mt0, __shfl_xor_sync(0xffffffffu, mt0, 2));
        mt1 = fmaxf(mt1, __shfl_xor_sync(0xffffffffu, mt1, 1));
        mt1 = fmaxf(mt1, __shfl_xor_sync(0xffffffffu, mt1, 2));

        const float mn0 = fmaxf(m0, mt0);
        const float mn1 = fmaxf(m1, mt1);
        const float al0 = __expf(m0 - mn0);
        const float al1 = __expf(m1 - mn1);
        m0 = mn0; m1 = mn1;

        float ps0 = 0.f, ps1 = 0.f;
        #pragma unroll
        for (int ni = 0; ni < 8; ni++) {
            c[ni][0] = __expf(c[ni][0] - mn0);
            c[ni][1] = __expf(c[ni][1] - mn0);
            c[ni][2] = __expf(c[ni][2] - mn1);
            c[ni][3] = __expf(c[ni][3] - mn1);
            ps0 += c[ni][0] + c[ni][1];
            ps1 += c[ni][2] + c[ni][3];
        }
        ps0 += __shfl_xor_sync(0xffffffffu, ps0, 1);
        ps0 += __shfl_xor_sync(0xffffffffu, ps0, 2);
        ps1 += __shfl_xor_sync(0xffffffffu, ps1, 1);
        ps1 += __shfl_xor_sync(0xffffffffu, ps1, 2);
        l0 = l0 * al0 + ps0;
        l1 = l1 * al1 + ps1;

        #pragma unroll
        for (int di = 0; di < 8; di++) {
            oacc[di][0] *= al0; oacc[di][1] *= al0;
            oacc[di][2] *= al1; oacc[di][3] *= al1;
        }

        #pragma unroll
        for (int st = 0; st < 4; st++) {
            uint32_t pa[4];
            pa[0] = pack_bf(c[2*st][0],   c[2*st][1]);
            pa[1] = pack_bf(c[2*st][2],   c[2*st][3]);
            pa[2] = pack_bf(c[2*st+1][0], c[2*st+1][1]);
            pa[3] = pack_bf(c[2*st+1][2], c[2*st+1][3]);
            #pragma unroll
            for (int di = 0; di < 8; di++) {
                const int nr = di * 8 + g;
                const int kc = st * 16 + tg * 2;
                uint32_t bf[2];
                bf[0] = *(const uint32_t*)&Vt[nr][kc];
                bf[1] = *(const uint32_t*)&Vt[nr][kc + 8];
                mma16816(oacc[di], pa, bf);
            }
        }
    }

    const float inv0 = 1.0f / l0;
    const float inv1 = 1.0f / l1;
    const size_t o0 = base + (size_t)qr0 * DD;
    const size_t o1 = o0 + 8 * DD;
    #pragma unroll
    for (int di = 0; di < 8; di++) {
        const int d = di * 8 + tg * 2;
        uint32_t lo;
        uint32_t hi = split_bf(oacc[di][0] * inv0, oacc[di][1] * inv0, lo);
        *(uint32_t*)(OH + o0 + d) = hi;
        *(uint32_t*)(OL + o0 + d) = lo;
        hi = split_bf(oacc[di][2] * inv1, oacc[di][3] * inv1, lo);
        *(uint32_t*)(OH + o1 + d) = hi;
        *(uint32_t*)(OL + o1 + d) = lo;
    }
}

// ---------------- block reduction helper ------------------------------------
__device__ __forceinline__ float block_sum256(float v) {
    __shared__ float red[8];
    #pragma unroll
    for (int off = 16; off; off >>= 1)
        v += __shfl_xor_sync(0xffffffffu, v, off);
    if ((threadIdx.x & 31) == 0) red[threadIdx.x >> 5] = v;
    __syncthreads();
    if (threadIdx.x < 32) {
        float t = (threadIdx.x < 8) ? red[threadIdx.x] : 0.0f;
        #pragma unroll
        for (int off = 4; off; off >>= 1)
            t += __shfl_xor_sync(0xffffffffu, t, off);
        if (threadIdx.x == 0) red[0] = t;
    }
    __syncthreads();
    float r = red[0];
    __syncthreads();
    return r;
}

// ---------------- LayerNorm (writes fp32 + bf16 hi/lo split) -----------------
__global__ __launch_bounds__(256)
void ln_kernel(const float* __restrict__ x, const float* __restrict__ g,
               const float* __restrict__ b, float* __restrict__ o,
               __nv_bfloat16* __restrict__ oH, __nv_bfloat16* __restrict__ oL)
{
    const int row = blockIdx.x;
    const int tid = threadIdx.x;
    const float* xr = x + (size_t)row * DD;
    float4 v = *(const float4*)(xr + tid * 4);

    float s = v.x + v.y + v.z + v.w;
    float mean = block_sum256(s) * (1.0f / DD);

    float dx = v.x - mean, dy = v.y - mean, dz = v.z - mean, dw = v.w - mean;
    float ss = dx*dx + dy*dy + dz*dz + dw*dw;
    float var = block_sum256(ss) * (1.0f / DD);
    float rstd = rsqrtf(var + 1e-5f);

    float4 gv = *(const float4*)(g + tid * 4);
    float4 bv = *(const float4*)(b + tid * 4);
    float4 ov;
    ov.x = dx * rstd * gv.x + bv.x;
    ov.y = dy * rstd * gv.y + bv.y;
    ov.z = dz * rstd * gv.z + bv.z;
    ov.w = dw * rstd * gv.w + bv.w;
    const size_t off = (size_t)row * DD + tid * 4;
    if (o) *(float4*)(o + off) = ov;
    uint32_t l0, l1;
    uint32_t h0 = split_bf(ov.x, ov.y, l0);
    uint32_t h1 = split_bf(ov.z, ov.w, l1);
    uint2 hh = { h0, h1 }, ll = { l0, l1 };
    *(uint2*)(oH + off) = hh;
    *(uint2*)(oL + off) = ll;
}

// ---------------- RoPE -------------------------------------------------------
__global__ __launch_bounds__(256)
void rope_kernel(float* __restrict__ x)
{
    const int idx  = blockIdx.x * blockDim.x + threadIdx.x;
    const int pair = idx & 511;
    const int row  = idx >> 9;
    const int t    = row & (TT - 1);
    const int i    = pair & 31;
    const float ang = (float)t * expf(-0.28782313662425537f * (float)i);
    float s, c;
    sincosf(ang, &s, &c);
    float2* p = (float2*)(x + ((size_t)row << 10) + (pair << 1));
    float2 v = *p;
    float2 o;
    o.x = v.x * c - v.y * s;
    o.y = v.x * s + v.y * c;
    *p = o;
}

// ---------------- launch ----------------------------------------------------
extern "C" void kernel_launch(void* const* d_in, const int* in_sizes, int n_in,
                              void* d_out, int out_size)
{
    const float* x   = (const float*)d_in[0];
    const unsigned char* mask = (const unsigned char*)d_in[1];
    const float* Wq  = (const float*)d_in[2];
    const float* bq  = (const float*)d_in[3];
    const float* Wk  = (const float*)d_in[4];
    const float* bk  = (const float*)d_in[5];
    const float* Wv  = (const float*)d_in[6];
    const float* bv  = (const float*)d_in[7];
    const float* Wo  = (const float*)d_in[8];
    const float* bo  = (const float*)d_in[9];
    const float* W1  = (const float*)d_in[10];
    const float* b1  = (const float*)d_in[11];
    const float* W2  = (const float*)d_in[12];
    const float* b2  = (const float*)d_in[13];
    const float* g1  = (const float*)d_in[14];
    const float* be1 = (const float*)d_in[15];
    const float* g2  = (const float*)d_in[16];
    const float* be2 = (const float*)d_in[17];
    float* out = (float*)d_out;

    float *h, *q, *k, *v, *x2;
    cudaGetSymbolAddress((void**)&h,  g_h);
    cudaGetSymbolAddress((void**)&q,  g_q);
    cudaGetSymbolAddress((void**)&k,  g_k);
    cudaGetSymbolAddress((void**)&v,  g_v);
    cudaGetSymbolAddress((void**)&x2, g_x2);

    __nv_bfloat16 *hH, *hL, *attH, *attL, *ffH, *ffL;
    __nv_bfloat16 *WqH, *WqL, *WkH, *WkL, *WvH, *WvL, *WoH, *WoL, *W1H, *W1L, *W2H, *W2L;
    cudaGetSymbolAddress((void**)&hH,   g_hH);   cudaGetSymbolAddress((void**)&hL,   g_hL);
    cudaGetSymbolAddress((void**)&attH, g_attH); cudaGetSymbolAddress((void**)&attL, g_attL);
    cudaGetSymbolAddress((void**)&ffH,  g_ffH);  cudaGetSymbolAddress((void**)&ffL,  g_ffL);
    cudaGetSymbolAddress((void**)&WqH,  g_WqH);  cudaGetSymbolAddress((void**)&WqL,  g_WqL);
    cudaGetSymbolAddress((void**)&WkH,  g_WkH);  cudaGetSymbolAddress((void**)&WkL,  g_WkL);
    cudaGetSymbolAddress((void**)&WvH,  g_WvH);  cudaGetSymbolAddress((void**)&WvL,  g_WvL);
    cudaGetSymbolAddress((void**)&WoH,  g_WoH);  cudaGetSymbolAddress((void**)&WoL,  g_WoL);
    cudaGetSymbolAddress((void**)&W1H,  g_W1H);  cudaGetSymbolAddress((void**)&W1L,  g_W1L);
    cudaGetSymbolAddress((void**)&W2H,  g_W2H);  cudaGetSymbolAddress((void**)&W2L,  g_W2L);

    const dim3 gD (DD  / BN, ROWS / BM);   // (8,64)
    const dim3 gDF(DFF / BN, ROWS / BM);   // (32,64)
    const int WD  = DD * DD / 4 / 256;     // blocks for DxD weight convert
    const int WDF = DD * DFF / 4 / 256;

    // 0) weight splits (cheap, memory-bound)
    convert_split<<<WD,  256>>>(Wq, WqH, WqL);
    convert_split<<<WD,  256>>>(Wk, WkH, WkL);
    convert_split<<<WD,  256>>>(Wv, WvH, WvL);
    convert_split<<<WD,  256>>>(Wo, WoH, WoL);
    convert_split<<<WDF, 256>>>(W1, W1H, W1L);
    convert_split<<<WDF, 256>>>(W2, W2H, W2L);

    // 1) h = LN(x)  (+ split)
    ln_kernel<<<ROWS, 256>>>(x, g1, be1, nullptr, hH, hL);
    // 2) q,k,v projections (fp32 out for rope/attention)
    gemm_bf<<<gD, 256>>>(hH, hL, WqH, WqL, bq, nullptr, q, nullptr, nullptr, DD, DD, 0);
    gemm_bf<<<gD, 256>>>(hH, hL, WkH, WkL, bk, nullptr, k, nullptr, nullptr, DD, DD, 0);
    gemm_bf<<<gD, 256>>>(hH, hL, WvH, WvL, bv, nullptr, v, nullptr, nullptr, DD, DD, 0);
    // 3) rope on q, k (in place)
    rope_kernel<<<(ROWS * DD / 2) / 256, 256>>>(q);
    rope_kernel<<<(ROWS * DD / 2) / 256, 256>>>(k);
    // 4) attention -> attH/attL (bf16 split)
    attn_mma<<<dim3(TT / 64, NH, BB), 128>>>(q, k, v, mask, attH, attL);
    // 5) x2 = x + att @ Wo^T + bo
    gemm_bf<<<gD, 256>>>(attH, attL, WoH, WoL, bo, x, x2, nullptr, nullptr, DD, DD, 0);
    // 6) h = LN(x2) (+ split)
    ln_kernel<<<ROWS, 256>>>(x2, g2, be2, nullptr, hH, hL);
    // 7) ff = gelu(h @ W1^T + b1) -> bf16 split only
    gemm_bf<<<gDF, 256>>>(hH, hL, W1H, W1L, b1, nullptr, nullptr, ffH, ffL, DFF, DD, 1);
    // 8) out = x2 + ff @ W2^T + b2
    gemm_bf<<<gD, 256>>>(ffH, ffL, W2H, W2L, b2, x2, out, nullptr, nullptr, DD, DFF, 0);
}

// round 11
// speedup vs baseline: 2.9881x; 1.0628x over previous
#include <cuda_runtime.h>
#include <cuda_bf16.h>
#include <math.h>
#include <stddef.h>
#include <stdint.h>

// Problem constants
#define BB    4
#define TT    2048
#define DD    1024
#define NH    16
#define DKH   64
#define DFF   4096
#define ROWS  (BB*TT)          // 8192

// ---------------- scratch (static device globals; no allocation allowed) ----
__device__ float g_h  [ (size_t)ROWS * DD ];
__device__ float g_q  [ (size_t)ROWS * DD ];
__device__ float g_k  [ (size_t)ROWS * DD ];
__device__ float g_v  [ (size_t)ROWS * DD ];
__device__ float g_x2 [ (size_t)ROWS * DD ];

__device__ __nv_bfloat16 g_hH  [ (size_t)ROWS * DD ];
__device__ __nv_bfloat16 g_hL  [ (size_t)ROWS * DD ];
__device__ __nv_bfloat16 g_attH[ (size_t)ROWS * DD ];
__device__ __nv_bfloat16 g_attL[ (size_t)ROWS * DD ];
__device__ __nv_bfloat16 g_ffH [ (size_t)ROWS * DFF ];
__device__ __nv_bfloat16 g_ffL [ (size_t)ROWS * DFF ];
__device__ __nv_bfloat16 g_WqH [ (size_t)DD * DD ];
__device__ __nv_bfloat16 g_WqL [ (size_t)DD * DD ];
__device__ __nv_bfloat16 g_WkH [ (size_t)DD * DD ];
__device__ __nv_bfloat16 g_WkL [ (size_t)DD * DD ];
__device__ __nv_bfloat16 g_WvH [ (size_t)DD * DD ];
__device__ __nv_bfloat16 g_WvL [ (size_t)DD * DD ];
__device__ __nv_bfloat16 g_WoH [ (size_t)DD * DD ];
__device__ __nv_bfloat16 g_WoL [ (size_t)DD * DD ];
__device__ __nv_bfloat16 g_W1H [ (size_t)DFF * DD ];
__device__ __nv_bfloat16 g_W1L [ (size_t)DFF * DD ];
__device__ __nv_bfloat16 g_W2H [ (size_t)DD * DFF ];
__device__ __nv_bfloat16 g_W2L [ (size_t)DD * DFF ];

__device__ __forceinline__ void mma16816(float* c, const uint32_t* a, const uint32_t* b) {
    asm volatile(
        "mma.sync.aligned.m16n8k16.row.col.f32.bf16.bf16.f32 "
        "{%0,%1,%2,%3}, {%4,%5,%6,%7}, {%8,%9}, {%0,%1,%2,%3};"
        : "+f"(c[0]), "+f"(c[1]), "+f"(c[2]), "+f"(c[3])
        : "r"(a[0]), "r"(a[1]), "r"(a[2]), "r"(a[3]), "r"(b[0]), "r"(b[1]));
}

__device__ __forceinline__ uint32_t pack_bf(float x, float y) {
    __nv_bfloat162 p = { __float2bfloat16(x), __float2bfloat16(y) };
    return *(uint32_t*)&p;
}
__device__ __forceinline__ uint32_t split_bf(float x, float y, uint32_t& lo) {
    __nv_bfloat16 hx = __float2bfloat16(x), hy = __float2bfloat16(y);
    __nv_bfloat162 h = { hx, hy };
    __nv_bfloat162 l = { __float2bfloat16(x - __bfloat162float(hx)),
                         __float2bfloat16(y - __bfloat162float(hy)) };
    lo = *(uint32_t*)&l;
    return *(uint32_t*)&h;
}

// ---------------- weight split conversion -----------------------------------
__global__ __launch_bounds__(256)
void convert_split(const float* __restrict__ src, __nv_bfloat16* __restrict__ H,
                   __nv_bfloat16* __restrict__ L)
{
    const int i = blockIdx.x * 256 + threadIdx.x;   // over float4s
    float4 v = ((const float4*)src)[i];
    uint32_t l0, l1;
    uint32_t h0 = split_bf(v.x, v.y, l0);
    uint32_t h1 = split_bf(v.z, v.w, l1);
    uint2 hh = { h0, h1 }, ll = { l0, l1 };
    *(uint2*)(H + (size_t)i * 4) = hh;
    *(uint2*)(L + (size_t)i * 4) = ll;
}

// ==================== bf16 MMA GEMM, double-buffered ========================
// C[M,N] = (AH+AL)[M,K] @ (BH+BL)[N,K]^T + bias (+res)(+gelu)
// acc = AhBh + AhBl + AlBh. Block 128x128, BK=32, 8 warps, warp tile 32x64.
// 2-stage smem pipeline: LDG(i+1) -> MMA(i) -> STS(i+1) -> sync.
#define BM 128
#define BN 128
#define BK 32
#define LDS_PAD 40
#define TILE_ELE   (BM * LDS_PAD)              // elems per tile
#define STAGE_ELE  (4 * TILE_ELE)              // Ah,Al,Bh,Bl
#define GEMM_SMEM  (2 * STAGE_ELE * 2)         // bytes (bf16)

__global__ __launch_bounds__(256)
void gemm_bf(const __nv_bfloat16* __restrict__ AH, const __nv_bfloat16* __restrict__ AL,
             const __nv_bfloat16* __restrict__ BH, const __nv_bfloat16* __restrict__ BL,
             const float* __restrict__ bias, const float* __restrict__ R,
             float* __restrict__ C, __nv_bfloat16* __restrict__ CH,
             __nv_bfloat16* __restrict__ CL, int Nc, int K, int gelu)
{
    extern __shared__ __nv_bfloat16 smp[];

    const int tid  = threadIdx.x;
    const int wid  = tid >> 5;
    const int lane = tid & 31;
    const int g    = lane >> 2;
    const int tg   = lane & 3;
    const int wm0  = (wid & 3) * 32;
    const int wn0  = (wid >> 2) * 64;
    const int bm   = blockIdx.y * BM;
    const int bn   = blockIdx.x * BN;

    // loader: thread t -> row t>>1, 16 bf16 starting (t&1)*16
    const int lrow = tid >> 1;
    const int lcol = (tid & 1) * 16;
    const size_t aoff = (size_t)(bm + lrow) * K + lcol;
    const size_t boff = (size_t)(bn + lrow) * K + lcol;
    const int lbase = lrow * LDS_PAD + lcol;

    float acc[2][8][4] = {};
    const int NIT = K / BK;

    uint4 pre[8];
    pre[0] = *(const uint4*)(AH + aoff);     pre[1] = *(const uint4*)(AH + aoff + 8);
    pre[2] = *(const uint4*)(AL + aoff);     pre[3] = *(const uint4*)(AL + aoff + 8);
    pre[4] = *(const uint4*)(BH + boff);     pre[5] = *(const uint4*)(BH + boff + 8);
    pre[6] = *(const uint4*)(BL + boff);     pre[7] = *(const uint4*)(BL + boff + 8);

    // fill stage 0
    {
        __nv_bfloat16* st = smp;
        *(uint4*)(st + 0*TILE_ELE + lbase)     = pre[0];
        *(uint4*)(st + 0*TILE_ELE + lbase + 8) = pre[1];
        *(uint4*)(st + 1*TILE_ELE + lbase)     = pre[2];
        *(uint4*)(st + 1*TILE_ELE + lbase + 8) = pre[3];
        *(uint4*)(st + 2*TILE_ELE + lbase)     = pre[4];
        *(uint4*)(st + 2*TILE_ELE + lbase + 8) = pre[5];
        *(uint4*)(st + 3*TILE_ELE + lbase)     = pre[6];
        *(uint4*)(st + 3*TILE_ELE + lbase + 8) = pre[7];
    }
    __syncthreads();

    for (int iter = 0; iter < NIT; iter++) {
        // issue global loads for next iteration (consumed after MMAs)
        const bool more = (iter + 1 < NIT);
        if (more) {
            const size_t an = aoff + (size_t)(iter + 1) * BK;
            const size_t bo = boff + (size_t)(iter + 1) * BK;
            pre[0] = *(const uint4*)(AH + an);     pre[1] = *(const uint4*)(AH + an + 8);
            pre[2] = *(const uint4*)(AL + an);     pre[3] = *(const uint4*)(AL + an + 8);
            pre[4] = *(const uint4*)(BH + bo);     pre[5] = *(const uint4*)(BH + bo + 8);
            pre[6] = *(const uint4*)(BL + bo);     pre[7] = *(const uint4*)(BL + bo + 8);
        }

        // compute on current stage
        const __nv_bfloat16* st = smp + (iter & 1) * STAGE_ELE;
        const __nv_bfloat16* Ah = st;
        const __nv_bfloat16* Al = st + TILE_ELE;
        const __nv_bfloat16* Bh = st + 2 * TILE_ELE;
        const __nv_bfloat16* Bl = st + 3 * TILE_ELE;

        #pragma unroll
        for (int k0 = 0; k0 < BK; k0 += 16) {
            uint32_t afh[2][4], afl[2][4];
            #pragma unroll
            for (int mi = 0; mi < 2; mi++) {
                const int r0 = (wm0 + mi * 16 + g) * LDS_PAD;
                const int c0 = k0 + tg * 2;
                afh[mi][0] = *(const uint32_t*)(Ah + r0 + c0);
                afh[mi][1] = *(const uint32_t*)(Ah + r0 + 8 * LDS_PAD + c0);
                afh[mi][2] = *(const uint32_t*)(Ah + r0 + c0 + 8);
                afh[mi][3] = *(const uint32_t*)(Ah + r0 + 8 * LDS_PAD + c0 + 8);
                afl[mi][0] = *(const uint32_t*)(Al + r0 + c0);
                afl[mi][1] = *(const uint32_t*)(Al + r0 + 8 * LDS_PAD + c0);
                afl[mi][2] = *(const uint32_t*)(Al + r0 + c0 + 8);
                afl[mi][3] = *(const uint32_t*)(Al + r0 + 8 * LDS_PAD + c0 + 8);
            }
            #pragma unroll
            for (int ni = 0; ni < 8; ni++) {
                const int nr = (wn0 + ni * 8 + g) * LDS_PAD;
                const int kc = k0 + tg * 2;
                uint32_t bfh[2], bfl[2];
                bfh[0] = *(const uint32_t*)(Bh + nr + kc);
                bfh[1] = *(const uint32_t*)(Bh + nr + kc + 8);
                bfl[0] = *(const uint32_t*)(Bl + nr + kc);
                bfl[1] = *(const uint32_t*)(Bl + nr + kc + 8);
                #pragma unroll
                for (int mi = 0; mi < 2; mi++) {
                    mma16816(acc[mi][ni], afh[mi], bfh);
                    mma16816(acc[mi][ni], afh[mi], bfl);
                    mma16816(acc[mi][ni], afl[mi], bfh);
                }
            }
        }

        // store next stage and sync once
        if (more) {
            __nv_bfloat16* nst = smp + ((iter + 1) & 1) * STAGE_ELE;
            *(uint4*)(nst + 0*TILE_ELE + lbase)     = pre[0];
            *(uint4*)(nst + 0*TILE_ELE + lbase + 8) = pre[1];
            *(uint4*)(nst + 1*TILE_ELE + lbase)     = pre[2];
            *(uint4*)(nst + 1*TILE_ELE + lbase + 8) = pre[3];
            *(uint4*)(nst + 2*TILE_ELE + lbase)     = pre[4];
            *(uint4*)(nst + 2*TILE_ELE + lbase + 8) = pre[5];
            *(uint4*)(nst + 3*TILE_ELE + lbase)     = pre[6];
            *(uint4*)(nst + 3*TILE_ELE + lbase + 8) = pre[7];
            __syncthreads();
        }
    }

    // epilogue
    #pragma unroll
    for (int mi = 0; mi < 2; mi++) {
        #pragma unroll
        for (int ni = 0; ni < 8; ni++) {
            const int n  = bn + wn0 + ni * 8 + tg * 2;
            const float bs0 = __ldg(bias + n), bs1 = __ldg(bias + n + 1);
            #pragma unroll
            for (int half = 0; half < 2; half++) {
                const int m = bm + wm0 + mi * 16 + g + half * 8;
                float v0 = acc[mi][ni][half * 2]     + bs0;
                float v1 = acc[mi][ni][half * 2 + 1] + bs1;
                if (R) {
                    const float* Rp = R + (size_t)m * Nc + n;
                    v0 += Rp[0]; v1 += Rp[1];
                }
                if (gelu) {
                    v0 = 0.5f * v0 * (1.0f + erff(v0 * 0.70710678118654752f));
                    v1 = 0.5f * v1 * (1.0f + erff(v1 * 0.70710678118654752f));
                }
                if (C) {
                    float2 o = { v0, v1 };
                    *(float2*)(C + (size_t)m * Nc + n) = o;
                }
                if (CH) {
                    uint32_t lo;
                    uint32_t hi = split_bf(v0, v1, lo);
                    *(uint32_t*)(CH + (size_t)m * Nc + n) = hi;
                    *(uint32_t*)(CL + (size_t)m * Nc + n) = lo;
                }
            }
        }
    }
}

// ==================== MMA flash attention ===================================
#define AS 64
#define APAD 72

__global__ __launch_bounds__(128)
void attn_mma(const float* __restrict__ Q, const float* __restrict__ K,
              const float* __restrict__ V, const unsigned char* __restrict__ mask,
              __nv_bfloat16* __restrict__ OH, __nv_bfloat16* __restrict__ OL)
{
    __shared__ __nv_bfloat16 Ks[AS][APAD];   // [s][d]
    __shared__ __nv_bfloat16 Vt[DKH][APAD];  // [d][s]
    __shared__ unsigned char Ms[AS];

    const int tid  = threadIdx.x;
    const int wid  = tid >> 5;
    const int lane = tid & 31;
    const int g    = lane >> 2;
    const int tg   = lane & 3;
    const int qt   = blockIdx.x;
    const int hh   = blockIdx.y;
    const int bb   = blockIdx.z;
    const int q0   = qt * 64;
    const size_t base = ((size_t)bb * TT) * DD + (size_t)hh * DKH;

    const int qr0 = q0 + wid * 16 + g;
    uint32_t qa[4][4];
    {
        const float* Qr0 = Q + base + (size_t)qr0 * DD;
        const float* Qr1 = Qr0 + 8 * DD;
        #pragma unroll
        for (int kt = 0; kt < 4; kt++) {
            const int c = kt * 16 + tg * 2;
            float2 x0 = *(const float2*)(Qr0 + c);
            float2 x1 = *(const float2*)(Qr1 + c);
            float2 x2 = *(const float2*)(Qr0 + c + 8);
            float2 x3 = *(const float2*)(Qr1 + c + 8);
            qa[kt][0] = pack_bf(x0.x * 0.125f, x0.y * 0.125f);
            qa[kt][1] = pack_bf(x1.x * 0.125f, x1.y * 0.125f);
            qa[kt][2] = pack_bf(x2.x * 0.125f, x2.y * 0.125f);
            qa[kt][3] = pack_bf(x3.x * 0.125f, x3.y * 0.125f);
        }
    }

    float m0 = -INFINITY, m1 = -INFINITY, l0 = 0.f, l1 = 0.f;
    float oacc[8][4] = {};

    const int lrow = tid >> 1;
    const int lcol = (tid & 1) * 32;

    for (int s0 = 0; s0 < TT; s0 += AS) {
        __syncthreads();
        {
            const float* Kr = K + base + (size_t)(s0 + lrow) * DD + lcol;
            const float* Vr = V + base + (size_t)(s0 + lrow) * DD + lcol;
            #pragma unroll
            for (int i = 0; i < 8; i++) {
                float4 kv = *(const float4*)(Kr + i * 4);
                *(uint32_t*)&Ks[lrow][lcol + i*4]     = pack_bf(kv.x, kv.y);
                *(uint32_t*)&Ks[lrow][lcol + i*4 + 2] = pack_bf(kv.z, kv.w);
                float4 vv = *(const float4*)(Vr + i * 4);
                Vt[lcol + i*4    ][lrow] = __float2bfloat16(vv.x);
                Vt[lcol + i*4 + 1][lrow] = __float2bfloat16(vv.y);
                Vt[lcol + i*4 + 2][lrow] = __float2bfloat16(vv.z);
                Vt[lcol + i*4 + 3][lrow] = __float2bfloat16(vv.w);
            }
            if (tid < AS) Ms[tid] = mask[(size_t)bb * TT + s0 + tid];
        }
        __syncthreads();

        float c[8][4] = {};
        #pragma unroll
        for (int ni = 0; ni < 8; ni++) {
            const int nr = ni * 8 + g;
            #pragma unroll
            for (int kt = 0; kt < 4; kt++) {
                const int kc = kt * 16 + tg * 2;
                uint32_t bf[2];
                bf[0] = *(const uint32_t*)&Ks[nr][kc];
                bf[1] = *(const uint32_t*)&Ks[nr][kc + 8];
                mma16816(c[ni], qa[kt], bf);
            }
        }

        float mt0 = -INFINITY, mt1 = -INFINITY;
        #pragma unroll
        for (int ni = 0; ni < 8; ni++) {
            const int sc0 = ni * 8 + tg * 2;
            if (Ms[sc0])     { c[ni][0] = -INFINITY; c[ni][2] = -INFINITY; }
            if (Ms[sc0 + 1]) { c[ni][1] = -INFINITY; c[ni][3] = -INFINITY; }
            mt0 = fmaxf(mt0, fmaxf(c[ni][0], c[ni][1]));
            mt1 = fmaxf(mt1, fmaxf(c[ni][2], c[ni][3]));
        }
        mt0 = fmaxf(mt0, __shfl_xor_sync(0xffffffffu, mt0, 1));
        mt0 = fmaxf(mt0, __shfl_xor_sync(0xffffffffu, mt0, 2));
        mt1 = fmaxf(mt1, __shfl_xor_sync(0xffffffffu, mt1, 1));
        mt1 = fmaxf(mt1, __shfl_xor_sync(0xffffffffu, mt1, 2));

        const float mn0 = fmaxf(m0, mt0);
        const float mn1 = fmaxf(m1, mt1);
        const float al0 = __expf(m0 - mn0);
        const float al1 = __expf(m1 - mn1);
        m0 = mn0; m1 = mn1;

        float ps0 = 0.f, ps1 = 0.f;
        #pragma unroll
        for (int ni = 0; ni < 8; ni++) {
            c[ni][0] = __expf(c[ni][0] - mn0);
            c[ni][1] = __expf(c[ni][1] - mn0);
            c[ni][2] = __expf(c[ni][2] - mn1);
            c[ni][3] = __expf(c[ni][3] - mn1);
            ps0 += c[ni][0] + c[ni][1];
            ps1 += c[ni][2] + c[ni][3];
        }
        ps0 += __shfl_xor_sync(0xffffffffu, ps0, 1);
        ps0 += __shfl_xor_sync(0xffffffffu, ps0, 2);
        ps1 += __shfl_xor_sync(0xffffffffu, ps1, 1);
        ps1 += __shfl_xor_sync(0xffffffffu, ps1, 2);
        l0 = l0 * al0 + ps0;
        l1 = l1 * al1 + ps1;

        #pragma unroll
        for (int di = 0; di < 8; di++) {
            oacc[di][0] *= al0; oacc[di][1] *= al0;
            oacc[di][2] *= al1; oacc[di][3] *= al1;
        }

        #pragma unroll
        for (int st = 0; st < 4; st++) {
            uint32_t pa[4];
            pa[0] = pack_bf(c[2*st][0],   c[2*st][1]);
            pa[1] = pack_bf(c[2*st][2],   c[2*st][3]);
            pa[2] = pack_bf(c[2*st+1][0], c[2*st+1][1]);
            pa[3] = pack_bf(c[2*st+1][2], c[2*st+1][3]);
            #pragma unroll
            for (int di = 0; di < 8; di++) {
                const int nr = di * 8 + g;
                const int kc = st * 16 + tg * 2;
                uint32_t bf[2];
                bf[0] = *(const uint32_t*)&Vt[nr][kc];
                bf[1] = *(const uint32_t*)&Vt[nr][kc + 8];
                mma16816(oacc[di], pa, bf);
            }
        }
    }

    const float inv0 = 1.0f / l0;
    const float inv1 = 1.0f / l1;
    const size_t o0 = base + (size_t)qr0 * DD;
    const size_t o1 = o0 + 8 * DD;
    #pragma unroll
    for (int di = 0; di < 8; di++) {
        const int d = di * 8 + tg * 2;
        uint32_t lo;
        uint32_t hi = split_bf(oacc[di][0] * inv0, oacc[di][1] * inv0, lo);
        *(uint32_t*)(OH + o0 + d) = hi;
        *(uint32_t*)(OL + o0 + d) = lo;
        hi = split_bf(oacc[di][2] * inv1, oacc[di][3] * inv1, lo);
        *(uint32_t*)(OH + o1 + d) = hi;
        *(uint32_t*)(OL + o1 + d) = lo;
    }
}

// ---------------- block reduction helper ------------------------------------
__device__ __forceinline__ float block_sum256(float v) {
    __shared__ float red[8];
    #pragma unroll
    for (int off = 16; off; off >>= 1)
        v += __shfl_xor_sync(0xffffffffu, v, off);
    if ((threadIdx.x & 31) == 0) red[threadIdx.x >> 5] = v;
    __syncthreads();
    if (threadIdx.x < 32) {
        float t = (threadIdx.x < 8) ? red[threadIdx.x] : 0.0f;
        #pragma unroll
        for (int off = 4; off; off >>= 1)
            t += __shfl_xor_sync(0xffffffffu, t, off);
        if (threadIdx.x == 0) red[0] = t;
    }
    __syncthreads();
    float r = red[0];
    __syncthreads();
    return r;
}

// ---------------- LayerNorm (writes fp32 + bf16 hi/lo split) -----------------
__global__ __launch_bounds__(256)
void ln_kernel(const float* __restrict__ x, const float* __restrict__ g,
               const float* __restrict__ b, float* __restrict__ o,
               __nv_bfloat16* __restrict__ oH, __nv_bfloat16* __restrict__ oL)
{
    const int row = blockIdx.x;
    const int tid = threadIdx.x;
    const float* xr = x + (size_t)row * DD;
    float4 v = *(const float4*)(xr + tid * 4);

    float s = v.x + v.y + v.z + v.w;
    float mean = block_sum256(s) * (1.0f / DD);

    float dx = v.x - mean, dy = v.y - mean, dz = v.z - mean, dw = v.w - mean;
    float ss = dx*dx + dy*dy + dz*dz + dw*dw;
    float var = block_sum256(ss) * (1.0f / DD);
    float rstd = rsqrtf(var + 1e-5f);

    float4 gv = *(const float4*)(g + tid * 4);
    float4 bv = *(const float4*)(b + tid * 4);
    float4 ov;
    ov.x = dx * rstd * gv.x + bv.x;
    ov.y = dy * rstd * gv.y + bv.y;
    ov.z = dz * rstd * gv.z + bv.z;
    ov.w = dw * rstd * gv.w + bv.w;
    const size_t off = (size_t)row * DD + tid * 4;
    if (o) *(float4*)(o + off) = ov;
    uint32_t l0, l1;
    uint32_t h0 = split_bf(ov.x, ov.y, l0);
    uint32_t h1 = split_bf(ov.z, ov.w, l1);
    uint2 hh = { h0, h1 }, ll = { l0, l1 };
    *(uint2*)(oH + off) = hh;
    *(uint2*)(oL + off) = ll;
}

// ---------------- RoPE -------------------------------------------------------
__global__ __launch_bounds__(256)
void rope_kernel(float* __restrict__ x)
{
    const int idx  = blockIdx.x * blockDim.x + threadIdx.x;
    const int pair = idx & 511;
    const int row  = idx >> 9;
    const int t    = row & (TT - 1);
    const int i    = pair & 31;
    const float ang = (float)t * expf(-0.28782313662425537f * (float)i);
    float s, c;
    sincosf(ang, &s, &c);
    float2* p = (float2*)(x + ((size_t)row << 10) + (pair << 1));
    float2 v = *p;
    float2 o;
    o.x = v.x * c - v.y * s;
    o.y = v.x * s + v.y * c;
    *p = o;
}

// ---------------- launch ----------------------------------------------------
extern "C" void kernel_launch(void* const* d_in, const int* in_sizes, int n_in,
                              void* d_out, int out_size)
{
    const float* x   = (const float*)d_in[0];
    const unsigned char* mask = (const unsigned char*)d_in[1];
    const float* Wq  = (const float*)d_in[2];
    const float* bq  = (const float*)d_in[3];
    const float* Wk  = (const float*)d_in[4];
    const float* bk  = (const float*)d_in[5];
    const float* Wv  = (const float*)d_in[6];
    const float* bv  = (const float*)d_in[7];
    const float* Wo  = (const float*)d_in[8];
    const float* bo  = (const float*)d_in[9];
    const float* W1  = (const float*)d_in[10];
    const float* b1  = (const float*)d_in[11];
    const float* W2  = (const float*)d_in[12];
    const float* b2  = (const float*)d_in[13];
    const float* g1  = (const float*)d_in[14];
    const float* be1 = (const float*)d_in[15];
    const float* g2  = (const float*)d_in[16];
    const float* be2 = (const float*)d_in[17];
    float* out = (float*)d_out;

    float *h, *q, *k, *v, *x2;
    cudaGetSymbolAddress((void**)&h,  g_h);
    cudaGetSymbolAddress((void**)&q,  g_q);
    cudaGetSymbolAddress((void**)&k,  g_k);
    cudaGetSymbolAddress((void**)&v,  g_v);
    cudaGetSymbolAddress((void**)&x2, g_x2);

    __nv_bfloat16 *hH, *hL, *attH, *attL, *ffH, *ffL;
    __nv_bfloat16 *WqH, *WqL, *WkH, *WkL, *WvH, *WvL, *WoH, *WoL, *W1H, *W1L, *W2H, *W2L;
    cudaGetSymbolAddress((void**)&hH,   g_hH);   cudaGetSymbolAddress((void**)&hL,   g_hL);
    cudaGetSymbolAddress((void**)&attH, g_attH); cudaGetSymbolAddress((void**)&attL, g_attL);
    cudaGetSymbolAddress((void**)&ffH,  g_ffH);  cudaGetSymbolAddress((void**)&ffL,  g_ffL);
    cudaGetSymbolAddress((void**)&WqH,  g_WqH);  cudaGetSymbolAddress((void**)&WqL,  g_WqL);
    cudaGetSymbolAddress((void**)&WkH,  g_WkH);  cudaGetSymbolAddress((void**)&WkL,  g_WkL);
    cudaGetSymbolAddress((void**)&WvH,  g_WvH);  cudaGetSymbolAddress((void**)&WvL,  g_WvL);
    cudaGetSymbolAddress((void**)&WoH,  g_WoH);  cudaGetSymbolAddress((void**)&WoL,  g_WoL);
    cudaGetSymbolAddress((void**)&W1H,  g_W1H);  cudaGetSymbolAddress((void**)&W1L,  g_W1L);
    cudaGetSymbolAddress((void**)&W2H,  g_W2H);  cudaGetSymbolAddress((void**)&W2L,  g_W2L);

    cudaFuncSetAttribute(gemm_bf, cudaFuncAttributeMaxDynamicSharedMemorySize, GEMM_SMEM);

    const dim3 gD (DD  / BN, ROWS / BM);   // (8,64)
    const dim3 gDF(DFF / BN, ROWS / BM);   // (32,64)
    const int WD  = DD * DD / 4 / 256;
    const int WDF = DD * DFF / 4 / 256;

    // 0) weight splits (cheap, memory-bound)
    convert_split<<<WD,  256>>>(Wq, WqH, WqL);
    convert_split<<<WD,  256>>>(Wk, WkH, WkL);
    convert_split<<<WD,  256>>>(Wv, WvH, WvL);
    convert_split<<<WD,  256>>>(Wo, WoH, WoL);
    convert_split<<<WDF, 256>>>(W1, W1H, W1L);
    convert_split<<<WDF, 256>>>(W2, W2H, W2L);

    // 1) h = LN(x)  (+ split)
    ln_kernel<<<ROWS, 256>>>(x, g1, be1, nullptr, hH, hL);
    // 2) q,k,v projections (fp32 out for rope/attention)
    gemm_bf<<<gD, 256, GEMM_SMEM>>>(hH, hL, WqH, WqL, bq, nullptr, q, nullptr, nullptr, DD, DD, 0);
    gemm_bf<<<gD, 256, GEMM_SMEM>>>(hH, hL, WkH, WkL, bk, nullptr, k, nullptr, nullptr, DD, DD, 0);
    gemm_bf<<<gD, 256, GEMM_SMEM>>>(hH, hL, WvH, WvL, bv, nullptr, v, nullptr, nullptr, DD, DD, 0);
    // 3) rope on q, k (in place)
    rope_kernel<<<(ROWS * DD / 2) / 256, 256>>>(q);
    rope_kernel<<<(ROWS * DD / 2) / 256, 256>>>(k);
    // 4) attention -> attH/attL (bf16 split)
    attn_mma<<<dim3(TT / 64, NH, BB), 128>>>(q, k, v, mask, attH, attL);
    // 5) x2 = x + att @ Wo^T + bo
    gemm_bf<<<gD, 256, GEMM_SMEM>>>(attH, attL, WoH, WoL, bo, x, x2, nullptr, nullptr, DD, DD, 0);
    // 6) h = LN(x2) (+ split)
    ln_kernel<<<ROWS, 256>>>(x2, g2, be2, nullptr, hH, hL);
    // 7) ff = gelu(h @ W1^T + b1) -> bf16 split only
    gemm_bf<<<gDF, 256, GEMM_SMEM>>>(hH, hL, W1H, W1L, b1, nullptr, nullptr, ffH, ffL, DFF, DD, 1);
    // 8) out = x2 + ff @ W2^T + b2
    gemm_bf<<<gD, 256, GEMM_SMEM>>>(ffH, ffL, W2H, W2L, b2, x2, out, nullptr, nullptr, DD, DFF, 0);
}

// round 13
// speedup vs baseline: 3.0513x; 1.0211x over previous
#include <cuda_runtime.h>
#include <cuda_bf16.h>
#include <math.h>
#include <stddef.h>
#include <stdint.h>

// Problem constants
#define BB    4
#define TT    2048
#define DD    1024
#define NH    16
#define DKH   64
#define DFF   4096
#define ROWS  (BB*TT)          // 8192

// ---------------- scratch (static device globals; no allocation allowed) ----
__device__ float g_h  [ (size_t)ROWS * DD ];
__device__ float g_q  [ (size_t)ROWS * DD ];
__device__ float g_k  [ (size_t)ROWS * DD ];
__device__ float g_v  [ (size_t)ROWS * DD ];
__device__ float g_x2 [ (size_t)ROWS * DD ];

__device__ __nv_bfloat16 g_hH  [ (size_t)ROWS * DD ];
__device__ __nv_bfloat16 g_hL  [ (size_t)ROWS * DD ];
__device__ __nv_bfloat16 g_attH[ (size_t)ROWS * DD ];
__device__ __nv_bfloat16 g_attL[ (size_t)ROWS * DD ];
__device__ __nv_bfloat16 g_ffH [ (size_t)ROWS * DFF ];
__device__ __nv_bfloat16 g_ffL [ (size_t)ROWS * DFF ];
__device__ __nv_bfloat16 g_WqH [ (size_t)DD * DD ];
__device__ __nv_bfloat16 g_WqL [ (size_t)DD * DD ];
__device__ __nv_bfloat16 g_WkH [ (size_t)DD * DD ];
__device__ __nv_bfloat16 g_WkL [ (size_t)DD * DD ];
__device__ __nv_bfloat16 g_WvH [ (size_t)DD * DD ];
__device__ __nv_bfloat16 g_WvL [ (size_t)DD * DD ];
__device__ __nv_bfloat16 g_WoH [ (size_t)DD * DD ];
__device__ __nv_bfloat16 g_WoL [ (size_t)DD * DD ];
__device__ __nv_bfloat16 g_W1H [ (size_t)DFF * DD ];
__device__ __nv_bfloat16 g_W1L [ (size_t)DFF * DD ];
__device__ __nv_bfloat16 g_W2H [ (size_t)DD * DFF ];
__device__ __nv_bfloat16 g_W2L [ (size_t)DD * DFF ];

__device__ __forceinline__ void mma16816(float* c, const uint32_t* a, const uint32_t* b) {
    asm volatile(
        "mma.sync.aligned.m16n8k16.row.col.f32.bf16.bf16.f32 "
        "{%0,%1,%2,%3}, {%4,%5,%6,%7}, {%8,%9}, {%0,%1,%2,%3};"
        : "+f"(c[0]), "+f"(c[1]), "+f"(c[2]), "+f"(c[3])
        : "r"(a[0]), "r"(a[1]), "r"(a[2]), "r"(a[3]), "r"(b[0]), "r"(b[1]));
}

__device__ __forceinline__ uint32_t pack_bf(float x, float y) {
    __nv_bfloat162 p = { __float2bfloat16(x), __float2bfloat16(y) };
    return *(uint32_t*)&p;
}
__device__ __forceinline__ uint32_t split_bf(float x, float y, uint32_t& lo) {
    __nv_bfloat16 hx = __float2bfloat16(x), hy = __float2bfloat16(y);
    __nv_bfloat162 h = { hx, hy };
    __nv_bfloat162 l = { __float2bfloat16(x - __bfloat162float(hx)),
                         __float2bfloat16(y - __bfloat162float(hy)) };
    lo = *(uint32_t*)&l;
    return *(uint32_t*)&h;
}

__device__ __forceinline__ void cp16(uint32_t saddr, const void* gaddr) {
    asm volatile("cp.async.cg.shared.global [%0], [%1], 16;"
                 :: "r"(saddr), "l"(gaddr));
}

// ---------------- weight split conversion -----------------------------------
__global__ __launch_bounds__(256)
void convert_split(const float* __restrict__ src, __nv_bfloat16* __restrict__ H,
                   __nv_bfloat16* __restrict__ L)
{
    const int i = blockIdx.x * 256 + threadIdx.x;   // over float4s
    float4 v = ((const float4*)src)[i];
    uint32_t l0, l1;
    uint32_t h0 = split_bf(v.x, v.y, l0);
    uint32_t h1 = split_bf(v.z, v.w, l1);
    uint2 hh = { h0, h1 }, ll = { l0, l1 };
    *(uint2*)(H + (size_t)i * 4) = hh;
    *(uint2*)(L + (size_t)i * 4) = ll;
}

// ==================== bf16 MMA GEMM, cp.async 3-stage =======================
// C[M,N] = (AH+AL)[M,K] @ (BH+BL)[N,K]^T + bias (+res)(+gelu)
// acc = AhBh + AhBl + AlBh. Block 128x128, BK=32, 8 warps, warp tile 32x64.
#define BM 128
#define BN 128
#define BK 32
#define LDS_PAD 40
#define NSTAGE 3
#define TILE_ELE   (BM * LDS_PAD)              // elems per tile
#define STAGE_ELE  (4 * TILE_ELE)              // Ah,Al,Bh,Bl
#define GEMM_SMEM  (NSTAGE * STAGE_ELE * 2)    // bytes (bf16) = 120KB

__global__ __launch_bounds__(256)
void gemm_bf(const __nv_bfloat16* __restrict__ AH, const __nv_bfloat16* __restrict__ AL,
             const __nv_bfloat16* __restrict__ BH, const __nv_bfloat16* __restrict__ BL,
             const float* __restrict__ bias, const float* __restrict__ R,
             float* __restrict__ C, __nv_bfloat16* __restrict__ CH,
             __nv_bfloat16* __restrict__ CL, int Nc, int K, int gelu)
{
    extern __shared__ __nv_bfloat16 smp[];
    const uint32_t sbase = (uint32_t)__cvta_generic_to_shared(smp);

    const int tid  = threadIdx.x;
    const int wid  = tid >> 5;
    const int lane = tid & 31;
    const int g    = lane >> 2;
    const int tg   = lane & 3;
    const int wm0  = (wid & 3) * 32;
    const int wn0  = (wid >> 2) * 64;
    const int bm   = blockIdx.y * BM;
    const int bn   = blockIdx.x * BN;

    // loader: thread t -> row t>>1, 16 bf16 starting (t&1)*16
    const int lrow = tid >> 1;
    const int lcol = (tid & 1) * 16;
    const size_t aoff = (size_t)(bm + lrow) * K + lcol;
    const size_t boff = (size_t)(bn + lrow) * K + lcol;
    const uint32_t lbase2 = (uint32_t)(lrow * LDS_PAD + lcol) * 2;   // bytes

    float acc[2][8][4] = {};
    const int NIT = K / BK;

    // issue one stage's 8 x 16B cp.async (wraps k index for tail dummies)
    #define ISSUE_STAGE(slot, kiter) do {                                   \
        const size_t _an = aoff + (size_t)(kiter) * BK;                     \
        const size_t _bo = boff + (size_t)(kiter) * BK;                     \
        const uint32_t _st = sbase + (uint32_t)(slot) * (STAGE_ELE * 2) + lbase2; \
        cp16(_st + 0*TILE_ELE*2,      AH + _an);                            \
        cp16(_st + 0*TILE_ELE*2 + 16, AH + _an + 8);                        \
        cp16(_st + 1*TILE_ELE*2,      AL + _an);                            \
        cp16(_st + 1*TILE_ELE*2 + 16, AL + _an + 8);                        \
        cp16(_st + 2*TILE_ELE*2,      BH + _bo);                            \
        cp16(_st + 2*TILE_ELE*2 + 16, BH + _bo + 8);                        \
        cp16(_st + 3*TILE_ELE*2,      BL + _bo);                            \
        cp16(_st + 3*TILE_ELE*2 + 16, BL + _bo + 8);                        \
        asm volatile("cp.async.commit_group;");                             \
    } while (0)

    ISSUE_STAGE(0, 0);
    ISSUE_STAGE(1, 1);
    asm volatile("cp.async.wait_group 1;");
    __syncthreads();                       // stage 0 visible to all

    for (int iter = 0; iter < NIT; iter++) {
        const __nv_bfloat16* st = smp + (iter % NSTAGE) * STAGE_ELE;
        const __nv_bfloat16* Ah = st;
        const __nv_bfloat16* Al = st + TILE_ELE;
        const __nv_bfloat16* Bh = st + 2 * TILE_ELE;
        const __nv_bfloat16* Bl = st + 3 * TILE_ELE;

        #pragma unroll
        for (int k0 = 0; k0 < BK; k0 += 16) {
            uint32_t afh[2][4], afl[2][4];
            #pragma unroll
            for (int mi = 0; mi < 2; mi++) {
                const int r0 = (wm0 + mi * 16 + g) * LDS_PAD;
                const int c0 = k0 + tg * 2;
                afh[mi][0] = *(const uint32_t*)(Ah + r0 + c0);
                afh[mi][1] = *(const uint32_t*)(Ah + r0 + 8 * LDS_PAD + c0);
                afh[mi][2] = *(const uint32_t*)(Ah + r0 + c0 + 8);
                afh[mi][3] = *(const uint32_t*)(Ah + r0 + 8 * LDS_PAD + c0 + 8);
                afl[mi][0] = *(const uint32_t*)(Al + r0 + c0);
                afl[mi][1] = *(const uint32_t*)(Al + r0 + 8 * LDS_PAD + c0);
                afl[mi][2] = *(const uint32_t*)(Al + r0 + c0 + 8);
                afl[mi][3] = *(const uint32_t*)(Al + r0 + 8 * LDS_PAD + c0 + 8);
            }
            #pragma unroll
            for (int ni = 0; ni < 8; ni++) {
                const int nr = (wn0 + ni * 8 + g) * LDS_PAD;
                const int kc = k0 + tg * 2;
                uint32_t bfh[2], bfl[2];
                bfh[0] = *(const uint32_t*)(Bh + nr + kc);
                bfh[1] = *(const uint32_t*)(Bh + nr + kc + 8);
                bfl[0] = *(const uint32_t*)(Bl + nr + kc);
                bfl[1] = *(const uint32_t*)(Bl + nr + kc + 8);
                #pragma unroll
                for (int mi = 0; mi < 2; mi++) {
                    mma16816(acc[mi][ni], afh[mi], bfh);
                    mma16816(acc[mi][ni], afh[mi], bfl);
                    mma16816(acc[mi][ni], afl[mi], bfh);
                }
            }
        }

        if (iter + 1 < NIT) {
            const int nx = iter + 2;
            ISSUE_STAGE((iter + 2) % NSTAGE, (nx < NIT) ? nx : 0);  // wrap: dummy
            asm volatile("cp.async.wait_group 1;");                // stage iter+1 ready
            __syncthreads();
        }
    }

    // epilogue
    #pragma unroll
    for (int mi = 0; mi < 2; mi++) {
        #pragma unroll
        for (int ni = 0; ni < 8; ni++) {
            const int n  = bn + wn0 + ni * 8 + tg * 2;
            const float bs0 = __ldg(bias + n), bs1 = __ldg(bias + n + 1);
            #pragma unroll
            for (int half = 0; half < 2; half++) {
                const int m = bm + wm0 + mi * 16 + g + half * 8;
                float v0 = acc[mi][ni][half * 2]     + bs0;
                float v1 = acc[mi][ni][half * 2 + 1] + bs1;
                if (R) {
                    const float* Rp = R + (size_t)m * Nc + n;
                    v0 += Rp[0]; v1 += Rp[1];
                }
                if (gelu) {
                    v0 = 0.5f * v0 * (1.0f + erff(v0 * 0.70710678118654752f));
                    v1 = 0.5f * v1 * (1.0f + erff(v1 * 0.70710678118654752f));
                }
                if (C) {
                    float2 o = { v0, v1 };
                    *(float2*)(C + (size_t)m * Nc + n) = o;
                }
                if (CH) {
                    uint32_t lo;
                    uint32_t hi = split_bf(v0, v1, lo);
                    *(uint32_t*)(CH + (size_t)m * Nc + n) = hi;
                    *(uint32_t*)(CL + (size_t)m * Nc + n) = lo;
                }
            }
        }
    }
}

// ==================== MMA flash attention ===================================
#define AS 64
#define APAD 72

__global__ __launch_bounds__(128)
void attn_mma(const float* __restrict__ Q, const float* __restrict__ K,
              const float* __restrict__ V, const unsigned char* __restrict__ mask,
              __nv_bfloat16* __restrict__ OH, __nv_bfloat16* __restrict__ OL)
{
    __shared__ __nv_bfloat16 Ks[AS][APAD];   // [s][d]
    __shared__ __nv_bfloat16 Vt[DKH][APAD];  // [d][s]
    __shared__ unsigned char Ms[AS];

    const int tid  = threadIdx.x;
    const int wid  = tid >> 5;
    const int lane = tid & 31;
    const int g    = lane >> 2;
    const int tg   = lane & 3;
    const int qt   = blockIdx.x;
    const int hh   = blockIdx.y;
    const int bb   = blockIdx.z;
    const int q0   = qt * 64;
    const size_t base = ((size_t)bb * TT) * DD + (size_t)hh * DKH;

    const int qr0 = q0 + wid * 16 + g;
    uint32_t qa[4][4];
    {
        const float* Qr0 = Q + base + (size_t)qr0 * DD;
        const float* Qr1 = Qr0 + 8 * DD;
        #pragma unroll
        for (int kt = 0; kt < 4; kt++) {
            const int c = kt * 16 + tg * 2;
            float2 x0 = *(const float2*)(Qr0 + c);
            float2 x1 = *(const float2*)(Qr1 + c);
            float2 x2 = *(const float2*)(Qr0 + c + 8);
            float2 x3 = *(const float2*)(Qr1 + c + 8);
            qa[kt][0] = pack_bf(x0.x * 0.125f, x0.y * 0.125f);
            qa[kt][1] = pack_bf(x1.x * 0.125f, x1.y * 0.125f);
            qa[kt][2] = pack_bf(x2.x * 0.125f, x2.y * 0.125f);
            qa[kt][3] = pack_bf(x3.x * 0.125f, x3.y * 0.125f);
        }
    }

    float m0 = -INFINITY, m1 = -INFINITY, l0 = 0.f, l1 = 0.f;
    float oacc[8][4] = {};

    const int lrow = tid >> 1;
    const int lcol = (tid & 1) * 32;

    for (int s0 = 0; s0 < TT; s0 += AS) {
        __syncthreads();
        {
            const float* Kr = K + base + (size_t)(s0 + lrow) * DD + lcol;
            const float* Vr = V + base + (size_t)(s0 + lrow) * DD + lcol;
            #pragma unroll
            for (int i = 0; i < 8; i++) {
                float4 kv = *(const float4*)(Kr + i * 4);
                *(uint32_t*)&Ks[lrow][lcol + i*4]     = pack_bf(kv.x, kv.y);
                *(uint32_t*)&Ks[lrow][lcol + i*4 + 2] = pack_bf(kv.z, kv.w);
                float4 vv = *(const float4*)(Vr + i * 4);
                Vt[lcol + i*4    ][lrow] = __float2bfloat16(vv.x);
                Vt[lcol + i*4 + 1][lrow] = __float2bfloat16(vv.y);
                Vt[lcol + i*4 + 2][lrow] = __float2bfloat16(vv.z);
                Vt[lcol + i*4 + 3][lrow] = __float2bfloat16(vv.w);
            }
            if (tid < AS) Ms[tid] = mask[(size_t)bb * TT + s0 + tid];
        }
        __syncthreads();

        float c[8][4] = {};
        #pragma unroll
        for (int ni = 0; ni < 8; ni++) {
            const int nr = ni * 8 + g;
            #pragma unroll
            for (int kt = 0; kt < 4; kt++) {
                const int kc = kt * 16 + tg * 2;
                uint32_t bf[2];
                bf[0] = *(const uint32_t*)&Ks[nr][kc];
                bf[1] = *(const uint32_t*)&Ks[nr][kc + 8];
                mma16816(c[ni], qa[kt], bf);
            }
        }

        float mt0 = -INFINITY, mt1 = -INFINITY;
        #pragma unroll
        for (int ni = 0; ni < 8; ni++) {
            const int sc0 = ni * 8 + tg * 2;
            if (Ms[sc0])     { c[ni][0] = -INFINITY; c[ni][2] = -INFINITY; }
            if (Ms[sc0 + 1]) { c[ni][1] = -INFINITY; c[ni][3] = -INFINITY; }
            mt0 = fmaxf(mt0, fmaxf(c[ni][0], c[ni][1]));
            mt1 = fmaxf(mt1, fmaxf(c[ni][2], c[ni][3]));
        }
        mt0 = fmaxf(mt0, __shfl_xor_sync(0xffffffffu, mt0, 1));
        mt0 = fmaxf(mt0, __shfl_xor_sync(0xffffffffu, mt0, 2));
        mt1 = fmaxf(mt1, __shfl_xor_sync(0xffffffffu, mt1, 1));
        mt1 = fmaxf(mt1, __shfl_xor_sync(0xffffffffu, mt1, 2));

        const float mn0 = fmaxf(m0, mt0);
        const float mn1 = fmaxf(m1, mt1);
        const float al0 = __expf(m0 - mn0);
        const float al1 = __expf(m1 - mn1);
        m0 = mn0; m1 = mn1;

        float ps0 = 0.f, ps1 = 0.f;
        #pragma unroll
        for (int ni = 0; ni < 8; ni++) {
            c[ni][0] = __expf(c[ni][0] - mn0);
            c[ni][1] = __expf(c[ni][1] - mn0);
            c[ni][2] = __expf(c[ni][2] - mn1);
            c[ni][3] = __expf(c[ni][3] - mn1);
            ps0 += c[ni][0] + c[ni][1];
            ps1 += c[ni][2] + c[ni][3];
        }
        ps0 += __shfl_xor_sync(0xffffffffu, ps0, 1);
        ps0 += __shfl_xor_sync(0xffffffffu, ps0, 2);
        ps1 += __shfl_xor_sync(0xffffffffu, ps1, 1);
        ps1 += __shfl_xor_sync(0xffffffffu, ps1, 2);
        l0 = l0 * al0 + ps0;
        l1 = l1 * al1 + ps1;

        #pragma unroll
        for (int di = 0; di < 8; di++) {
            oacc[di][0] *= al0; oacc[di][1] *= al0;
            oacc[di][2] *= al1; oacc[di][3] *= al1;
        }

        #pragma unroll
        for (int st = 0; st < 4; st++) {
            uint32_t pa[4];
            pa[0] = pack_bf(c[2*st][0],   c[2*st][1]);
            pa[1] = pack_bf(c[2*st][2],   c[2*st][3]);
            pa[2] = pack_bf(c[2*st+1][0], c[2*st+1][1]);
            pa[3] = pack_bf(c[2*st+1][2], c[2*st+1][3]);
            #pragma unroll
            for (int di = 0; di < 8; di++) {
                const int nr = di * 8 + g;
                const int kc = st * 16 + tg * 2;
                uint32_t bf[2];
                bf[0] = *(const uint32_t*)&Vt[nr][kc];
                bf[1] = *(const uint32_t*)&Vt[nr][kc + 8];
                mma16816(oacc[di], pa, bf);
            }
        }
    }

    const float inv0 = 1.0f / l0;
    const float inv1 = 1.0f / l1;
    const size_t o0 = base + (size_t)qr0 * DD;
    const size_t o1 = o0 + 8 * DD;
    #pragma unroll
    for (int di = 0; di < 8; di++) {
        const int d = di * 8 + tg * 2;
        uint32_t lo;
        uint32_t hi = split_bf(oacc[di][0] * inv0, oacc[di][1] * inv0, lo);
        *(uint32_t*)(OH + o0 + d) = hi;
        *(uint32_t*)(OL + o0 + d) = lo;
        hi = split_bf(oacc[di][2] * inv1, oacc[di][3] * inv1, lo);
        *(uint32_t*)(OH + o1 + d) = hi;
        *(uint32_t*)(OL + o1 + d) = lo;
    }
}

// ---------------- block reduction helper ------------------------------------
__device__ __forceinline__ float block_sum256(float v) {
    __shared__ float red[8];
    #pragma unroll
    for (int off = 16; off; off >>= 1)
        v += __shfl_xor_sync(0xffffffffu, v, off);
    if ((threadIdx.x & 31) == 0) red[threadIdx.x >> 5] = v;
    __syncthreads();
    if (threadIdx.x < 32) {
        float t = (threadIdx.x < 8) ? red[threadIdx.x] : 0.0f;
        #pragma unroll
        for (int off = 4; off; off >>= 1)
            t += __shfl_xor_sync(0xffffffffu, t, off);
        if (threadIdx.x == 0) red[0] = t;
    }
    __syncthreads();
    float r = red[0];
    __syncthreads();
    return r;
}

// ---------------- LayerNorm (writes fp32 + bf16 hi/lo split) -----------------
__global__ __launch_bounds__(256)
void ln_kernel(const float* __restrict__ x, const float* __restrict__ g,
               const float* __restrict__ b, float* __restrict__ o,
               __nv_bfloat16* __restrict__ oH, __nv_bfloat16* __restrict__ oL)
{
    const int row = blockIdx.x;
    const int tid = threadIdx.x;
    const float* xr = x + (size_t)row * DD;
    float4 v = *(const float4*)(xr + tid * 4);

    float s = v.x + v.y + v.z + v.w;
    float mean = block_sum256(s) * (1.0f / DD);

    float dx = v.x - mean, dy = v.y - mean, dz = v.z - mean, dw = v.w - mean;
    float ss = dx*dx + dy*dy + dz*dz + dw*dw;
    float var = block_sum256(ss) * (1.0f / DD);
    float rstd = rsqrtf(var + 1e-5f);

    float4 gv = *(const float4*)(g + tid * 4);
    float4 bv = *(const float4*)(b + tid * 4);
    float4 ov;
    ov.x = dx * rstd * gv.x + bv.x;
    ov.y = dy * rstd * gv.y + bv.y;
    ov.z = dz * rstd * gv.z + bv.z;
    ov.w = dw * rstd * gv.w + bv.w;
    const size_t off = (size_t)row * DD + tid * 4;
    if (o) *(float4*)(o + off) = ov;
    uint32_t l0, l1;
    uint32_t h0 = split_bf(ov.x, ov.y, l0);
    uint32_t h1 = split_bf(ov.z, ov.w, l1);
    uint2 hh = { h0, h1 }, ll = { l0, l1 };
    *(uint2*)(oH + off) = hh;
    *(uint2*)(oL + off) = ll;
}

// ---------------- RoPE -------------------------------------------------------
__global__ __launch_bounds__(256)
void rope_kernel(float* __restrict__ x)
{
    const int idx  = blockIdx.x * blockDim.x + threadIdx.x;
    const int pair = idx & 511;
    const int row  = idx >> 9;
    const int t    = row & (TT - 1);
    const int i    = pair & 31;
    const float ang = (float)t * expf(-0.28782313662425537f * (float)i);
    float s, c;
    sincosf(ang, &s, &c);
    float2* p = (float2*)(x + ((size_t)row << 10) + (pair << 1));
    float2 v = *p;
    float2 o;
    o.x = v.x * c - v.y * s;
    o.y = v.x * s + v.y * c;
    *p = o;
}

// ---------------- launch ----------------------------------------------------
extern "C" void kernel_launch(void* const* d_in, const int* in_sizes, int n_in,
                              void* d_out, int out_size)
{
    const float* x   = (const float*)d_in[0];
    const unsigned char* mask = (const unsigned char*)d_in[1];
    const float* Wq  = (const float*)d_in[2];
    const float* bq  = (const float*)d_in[3];
    const float* Wk  = (const float*)d_in[4];
    const float* bk  = (const float*)d_in[5];
    const float* Wv  = (const float*)d_in[6];
    const float* bv  = (const float*)d_in[7];
    const float* Wo  = (const float*)d_in[8];
    const float* bo  = (const float*)d_in[9];
    const float* W1  = (const float*)d_in[10];
    const float* b1  = (const float*)d_in[11];
    const float* W2  = (const float*)d_in[12];
    const float* b2  = (const float*)d_in[13];
    const float* g1  = (const float*)d_in[14];
    const float* be1 = (const float*)d_in[15];
    const float* g2  = (const float*)d_in[16];
    const float* be2 = (const float*)d_in[17];
    float* out = (float*)d_out;

    float *h, *q, *k, *v, *x2;
    cudaGetSymbolAddress((void**)&h,  g_h);
    cudaGetSymbolAddress((void**)&q,  g_q);
    cudaGetSymbolAddress((void**)&k,  g_k);
    cudaGetSymbolAddress((void**)&v,  g_v);
    cudaGetSymbolAddress((void**)&x2, g_x2);

    __nv_bfloat16 *hH, *hL, *attH, *attL, *ffH, *ffL;
    __nv_bfloat16 *WqH, *WqL, *WkH, *WkL, *WvH, *WvL, *WoH, *WoL, *W1H, *W1L, *W2H, *W2L;
    cudaGetSymbolAddress((void**)&hH,   g_hH);   cudaGetSymbolAddress((void**)&hL,   g_hL);
    cudaGetSymbolAddress((void**)&attH, g_attH); cudaGetSymbolAddress((void**)&attL, g_attL);
    cudaGetSymbolAddress((void**)&ffH,  g_ffH);  cudaGetSymbolAddress((void**)&ffL,  g_ffL);
    cudaGetSymbolAddress((void**)&WqH,  g_WqH);  cudaGetSymbolAddress((void**)&WqL,  g_WqL);
    cudaGetSymbolAddress((void**)&WkH,  g_WkH);  cudaGetSymbolAddress((void**)&WkL,  g_WkL);
    cudaGetSymbolAddress((void**)&WvH,  g_WvH);  cudaGetSymbolAddress((void**)&WvL,  g_WvL);
    cudaGetSymbolAddress((void**)&WoH,  g_WoH);  cudaGetSymbolAddress((void**)&WoL,  g_WoL);
    cudaGetSymbolAddress((void**)&W1H,  g_W1H);  cudaGetSymbolAddress((void**)&W1L,  g_W1L);
    cudaGetSymbolAddress((void**)&W2H,  g_W2H);  cudaGetSymbolAddress((void**)&W2L,  g_W2L);

    cudaFuncSetAttribute(gemm_bf, cudaFuncAttributeMaxDynamicSharedMemorySize, GEMM_SMEM);

    const dim3 gD (DD  / BN, ROWS / BM);   // (8,64)
    const dim3 gDF(DFF / BN, ROWS / BM);   // (32,64)
    const int WD  = DD * DD / 4 / 256;
    const int WDF = DD * DFF / 4 / 256;

    // 0) weight splits (cheap, memory-bound)
    convert_split<<<WD,  256>>>(Wq, WqH, WqL);
    convert_split<<<WD,  256>>>(Wk, WkH, WkL);
    convert_split<<<WD,  256>>>(Wv, WvH, WvL);
    convert_split<<<WD,  256>>>(Wo, WoH, WoL);
    convert_split<<<WDF, 256>>>(W1, W1H, W1L);
    convert_split<<<WDF, 256>>>(W2, W2H, W2L);

    // 1) h = LN(x)  (+ split)
    ln_kernel<<<ROWS, 256>>>(x, g1, be1, nullptr, hH, hL);
    // 2) q,k,v projections (fp32 out for rope/attention)
    gemm_bf<<<gD, 256, GEMM_SMEM>>>(hH, hL, WqH, WqL, bq, nullptr, q, nullptr, nullptr, DD, DD, 0);
    gemm_bf<<<gD, 256, GEMM_SMEM>>>(hH, hL, WkH, WkL, bk, nullptr, k, nullptr, nullptr, DD, DD, 0);
    gemm_bf<<<gD, 256, GEMM_SMEM>>>(hH, hL, WvH, WvL, bv, nullptr, v, nullptr, nullptr, DD, DD, 0);
    // 3) rope on q, k (in place)
    rope_kernel<<<(ROWS * DD / 2) / 256, 256>>>(q);
    rope_kernel<<<(ROWS * DD / 2) / 256, 256>>>(k);
    // 4) attention -> attH/attL (bf16 split)
    attn_mma<<<dim3(TT / 64, NH, BB), 128>>>(q, k, v, mask, attH, attL);
    // 5) x2 = x + att @ Wo^T + bo
    gemm_bf<<<gD, 256, GEMM_SMEM>>>(attH, attL, WoH, WoL, bo, x, x2, nullptr, nullptr, DD, DD, 0);
    // 6) h = LN(x2) (+ split)
    ln_kernel<<<ROWS, 256>>>(x2, g2, be2, nullptr, hH, hL);
    // 7) ff = gelu(h @ W1^T + b1) -> bf16 split only
    gemm_bf<<<gDF, 256, GEMM_SMEM>>>(hH, hL, W1H, W1L, b1, nullptr, nullptr, ffH, ffL, DFF, DD, 1);
    // 8) out = x2 + ff @ W2^T + b2
    gemm_bf<<<gD, 256, GEMM_SMEM>>>(ffH, ffL, W2H, W2L, b2, x2, out, nullptr, nullptr, DD, DFF, 0);
}

// round 17
// speedup vs baseline: 5.6947x; 1.8663x over previous
#include <cuda_runtime.h>
#include <cuda_bf16.h>
#include <cuda_fp16.h>
#include <math.h>
#include <stddef.h>
#include <stdint.h>

// Problem constants
#define BB    4
#define TT    2048
#define DD    1024
#define NH    16
#define DKH   64
#define DFF   4096
#define ROWS  (BB*TT)          // 8192

// ---------------- scratch (static device globals; no allocation allowed) ----
__device__ float g_q  [ (size_t)ROWS * DD ];
__device__ float g_k  [ (size_t)ROWS * DD ];
__device__ float g_v  [ (size_t)ROWS * DD ];
__device__ float g_x2 [ (size_t)ROWS * DD ];

__device__ __half g_hF  [ (size_t)ROWS * DD ];
__device__ __half g_attF[ (size_t)ROWS * DD ];
__device__ __half g_ffF [ (size_t)ROWS * DFF ];
__device__ __half g_WqF [ (size_t)DD * DD ];
__device__ __half g_WkF [ (size_t)DD * DD ];
__device__ __half g_WvF [ (size_t)DD * DD ];
__device__ __half g_WoF [ (size_t)DD * DD ];
__device__ __half g_W1F [ (size_t)DFF * DD ];
__device__ __half g_W2F [ (size_t)DD * DFF ];

// fp16 MMA (same fragment layout as bf16 variant)
__device__ __forceinline__ void mma16816h(float* c, const uint32_t* a, const uint32_t* b) {
    asm volatile(
        "mma.sync.aligned.m16n8k16.row.col.f32.f16.f16.f32 "
        "{%0,%1,%2,%3}, {%4,%5,%6,%7}, {%8,%9}, {%0,%1,%2,%3};"
        : "+f"(c[0]), "+f"(c[1]), "+f"(c[2]), "+f"(c[3])
        : "r"(a[0]), "r"(a[1]), "r"(a[2]), "r"(a[3]), "r"(b[0]), "r"(b[1]));
}
// bf16 MMA (attention, unchanged)
__device__ __forceinline__ void mma16816(float* c, const uint32_t* a, const uint32_t* b) {
    asm volatile(
        "mma.sync.aligned.m16n8k16.row.col.f32.bf16.bf16.f32 "
        "{%0,%1,%2,%3}, {%4,%5,%6,%7}, {%8,%9}, {%0,%1,%2,%3};"
        : "+f"(c[0]), "+f"(c[1]), "+f"(c[2]), "+f"(c[3])
        : "r"(a[0]), "r"(a[1]), "r"(a[2]), "r"(a[3]), "r"(b[0]), "r"(b[1]));
}

__device__ __forceinline__ uint32_t pack_bf(float x, float y) {
    __nv_bfloat162 p = { __float2bfloat16(x), __float2bfloat16(y) };
    return *(uint32_t*)&p;
}
__device__ __forceinline__ uint32_t pack_hf(float x, float y) {
    __half2 p = __floats2half2_rn(x, y);
    return *(uint32_t*)&p;
}

__device__ __forceinline__ void cp16(uint32_t saddr, const void* gaddr) {
    asm volatile("cp.async.cg.shared.global [%0], [%1], 16;"
                 :: "r"(saddr), "l"(gaddr));
}

// ---------------- weight conversion fp32 -> fp16 -----------------------------
__global__ __launch_bounds__(256)
void convert_half(const float* __restrict__ src, __half* __restrict__ H)
{
    const int i = blockIdx.x * 256 + threadIdx.x;   // over float4s
    float4 v = ((const float4*)src)[i];
    uint2 hh = { pack_hf(v.x, v.y), pack_hf(v.z, v.w) };
    *(uint2*)(H + (size_t)i * 4) = hh;
}

// ==================== fp16 MMA GEMM, cp.async 3-stage =======================
// C[M,N] = A[M,K] @ B[N,K]^T + bias (+res)(+gelu), single fp16 pass.
// Block 128x128, BK=32, 8 warps, warp tile 32x64.
#define BM 128
#define BN 128
#define BK 32
#define LDS_PAD 40
#define NSTAGE 3
#define TILE_ELE   (BM * LDS_PAD)              // elems per tile
#define STAGE_ELE  (2 * TILE_ELE)              // A, B
#define GEMM_SMEM  (NSTAGE * STAGE_ELE * 2)    // bytes = 61440

__global__ __launch_bounds__(256)
void gemm_hf(const __half* __restrict__ A, const __half* __restrict__ B,
             const float* __restrict__ bias, const float* __restrict__ R,
             float* __restrict__ C, __half* __restrict__ CF,
             int Nc, int K, int gelu)
{
    extern __shared__ __half smp[];
    const uint32_t sbase = (uint32_t)__cvta_generic_to_shared(smp);

    const int tid  = threadIdx.x;
    const int wid  = tid >> 5;
    const int lane = tid & 31;
    const int g    = lane >> 2;
    const int tg   = lane & 3;
    const int wm0  = (wid & 3) * 32;
    const int wn0  = (wid >> 2) * 64;
    const int bm   = blockIdx.y * BM;
    const int bn   = blockIdx.x * BN;

    // loader: thread t -> row t>>1, 16 halves starting (t&1)*16
    const int lrow = tid >> 1;
    const int lcol = (tid & 1) * 16;
    const size_t aoff = (size_t)(bm + lrow) * K + lcol;
    const size_t boff = (size_t)(bn + lrow) * K + lcol;
    const uint32_t lbase2 = (uint32_t)(lrow * LDS_PAD + lcol) * 2;   // bytes

    float acc[2][8][4] = {};
    const int NIT = K / BK;

    #define ISSUE_STAGE(slot, kiter) do {                                   \
        const size_t _an = aoff + (size_t)(kiter) * BK;                     \
        const size_t _bo = boff + (size_t)(kiter) * BK;                     \
        const uint32_t _st = sbase + (uint32_t)(slot) * (STAGE_ELE * 2) + lbase2; \
        cp16(_st,                     A + _an);                             \
        cp16(_st + 16,                A + _an + 8);                         \
        cp16(_st + TILE_ELE*2,        B + _bo);                             \
        cp16(_st + TILE_ELE*2 + 16,   B + _bo + 8);                         \
        asm volatile("cp.async.commit_group;");                             \
    } while (0)

    ISSUE_STAGE(0, 0);
    ISSUE_STAGE(1, 1);
    asm volatile("cp.async.wait_group 1;");
    __syncthreads();                       // stage 0 visible to all

    for (int iter = 0; iter < NIT; iter++) {
        const __half* st = smp + (iter % NSTAGE) * STAGE_ELE;
        const __half* As = st;
        const __half* Bs = st + TILE_ELE;

        #pragma unroll
        for (int k0 = 0; k0 < BK; k0 += 16) {
            uint32_t af[2][4];
            #pragma unroll
            for (int mi = 0; mi < 2; mi++) {
                const int r0 = (wm0 + mi * 16 + g) * LDS_PAD;
                const int c0 = k0 + tg * 2;
                af[mi][0] = *(const uint32_t*)(As + r0 + c0);
                af[mi][1] = *(const uint32_t*)(As + r0 + 8 * LDS_PAD + c0);
                af[mi][2] = *(const uint32_t*)(As + r0 + c0 + 8);
                af[mi][3] = *(const uint32_t*)(As + r0 + 8 * LDS_PAD + c0 + 8);
            }
            #pragma unroll
            for (int ni = 0; ni < 8; ni++) {
                const int nr = (wn0 + ni * 8 + g) * LDS_PAD;
                const int kc = k0 + tg * 2;
                uint32_t bf[2];
                bf[0] = *(const uint32_t*)(Bs + nr + kc);
                bf[1] = *(const uint32_t*)(Bs + nr + kc + 8);
                mma16816h(acc[0][ni], af[0], bf);
                mma16816h(acc[1][ni], af[1], bf);
            }
        }

        if (iter + 1 < NIT) {
            const int nx = iter + 2;
            ISSUE_STAGE((iter + 2) % NSTAGE, (nx < NIT) ? nx : 0);  // wrap: dummy
            asm volatile("cp.async.wait_group 1;");                // stage iter+1 ready
            __syncthreads();
        }
    }

    // epilogue
    #pragma unroll
    for (int mi = 0; mi < 2; mi++) {
        #pragma unroll
        for (int ni = 0; ni < 8; ni++) {
            const int n  = bn + wn0 + ni * 8 + tg * 2;
            const float bs0 = __ldg(bias + n), bs1 = __ldg(bias + n + 1);
            #pragma unroll
            for (int half_ = 0; half_ < 2; half_++) {
                const int m = bm + wm0 + mi * 16 + g + half_ * 8;
                float v0 = acc[mi][ni][half_ * 2]     + bs0;
                float v1 = acc[mi][ni][half_ * 2 + 1] + bs1;
                if (R) {
                    const float* Rp = R + (size_t)m * Nc + n;
                    v0 += Rp[0]; v1 += Rp[1];
                }
                if (gelu) {
                    v0 = 0.5f * v0 * (1.0f + erff(v0 * 0.70710678118654752f));
                    v1 = 0.5f * v1 * (1.0f + erff(v1 * 0.70710678118654752f));
                }
                if (C) {
                    float2 o = { v0, v1 };
                    *(float2*)(C + (size_t)m * Nc + n) = o;
                }
                if (CF) {
                    *(uint32_t*)(CF + (size_t)m * Nc + n) = pack_hf(v0, v1);
                }
            }
        }
    }
}

// ==================== MMA flash attention (bf16 internals) ==================
#define AS 64
#define APAD 72

__global__ __launch_bounds__(128)
void attn_mma(const float* __restrict__ Q, const float* __restrict__ K,
              const float* __restrict__ V, const unsigned char* __restrict__ mask,
              __half* __restrict__ OF)
{
    __shared__ __nv_bfloat16 Ks[AS][APAD];   // [s][d]
    __shared__ __nv_bfloat16 Vt[DKH][APAD];  // [d][s]
    __shared__ unsigned char Ms[AS];

    const int tid  = threadIdx.x;
    const int wid  = tid >> 5;
    const int lane = tid & 31;
    const int g    = lane >> 2;
    const int tg   = lane & 3;
    const int qt   = blockIdx.x;
    const int hh   = blockIdx.y;
    const int bb   = blockIdx.z;
    const int q0   = qt * 64;
    const size_t base = ((size_t)bb * TT) * DD + (size_t)hh * DKH;

    const int qr0 = q0 + wid * 16 + g;
    uint32_t qa[4][4];
    {
        const float* Qr0 = Q + base + (size_t)qr0 * DD;
        const float* Qr1 = Qr0 + 8 * DD;
        #pragma unroll
        for (int kt = 0; kt < 4; kt++) {
            const int c = kt * 16 + tg * 2;
            float2 x0 = *(const float2*)(Qr0 + c);
            float2 x1 = *(const float2*)(Qr1 + c);
            float2 x2 = *(const float2*)(Qr0 + c + 8);
            float2 x3 = *(const float2*)(Qr1 + c + 8);
            qa[kt][0] = pack_bf(x0.x * 0.125f, x0.y * 0.125f);
            qa[kt][1] = pack_bf(x1.x * 0.125f, x1.y * 0.125f);
            qa[kt][2] = pack_bf(x2.x * 0.125f, x2.y * 0.125f);
            qa[kt][3] = pack_bf(x3.x * 0.125f, x3.y * 0.125f);
        }
    }

    float m0 = -INFINITY, m1 = -INFINITY, l0 = 0.f, l1 = 0.f;
    float oacc[8][4] = {};

    const int lrow = tid >> 1;
    const int lcol = (tid & 1) * 32;

    for (int s0 = 0; s0 < TT; s0 += AS) {
        __syncthreads();
        {
            const float* Kr = K + base + (size_t)(s0 + lrow) * DD + lcol;
            const float* Vr = V + base + (size_t)(s0 + lrow) * DD + lcol;
            #pragma unroll
            for (int i = 0; i < 8; i++) {
                float4 kv = *(const float4*)(Kr + i * 4);
                *(uint32_t*)&Ks[lrow][lcol + i*4]     = pack_bf(kv.x, kv.y);
                *(uint32_t*)&Ks[lrow][lcol + i*4 + 2] = pack_bf(kv.z, kv.w);
                float4 vv = *(const float4*)(Vr + i * 4);
                Vt[lcol + i*4    ][lrow] = __float2bfloat16(vv.x);
                Vt[lcol + i*4 + 1][lrow] = __float2bfloat16(vv.y);
                Vt[lcol + i*4 + 2][lrow] = __float2bfloat16(vv.z);
                Vt[lcol + i*4 + 3][lrow] = __float2bfloat16(vv.w);
            }
            if (tid < AS) Ms[tid] = mask[(size_t)bb * TT + s0 + tid];
        }
        __syncthreads();

        float c[8][4] = {};
        #pragma unroll
        for (int ni = 0; ni < 8; ni++) {
            const int nr = ni * 8 + g;
            #pragma unroll
            for (int kt = 0; kt < 4; kt++) {
                const int kc = kt * 16 + tg * 2;
                uint32_t bf[2];
                bf[0] = *(const uint32_t*)&Ks[nr][kc];
                bf[1] = *(const uint32_t*)&Ks[nr][kc + 8];
                mma16816(c[ni], qa[kt], bf);
            }
        }

        float mt0 = -INFINITY, mt1 = -INFINITY;
        #pragma unroll
        for (int ni = 0; ni < 8; ni++) {
            const int sc0 = ni * 8 + tg * 2;
            if (Ms[sc0])     { c[ni][0] = -INFINITY; c[ni][2] = -INFINITY; }
            if (Ms[sc0 + 1]) { c[ni][1] = -INFINITY; c[ni][3] = -INFINITY; }
            mt0 = fmaxf(mt0, fmaxf(c[ni][0], c[ni][1]));
            mt1 = fmaxf(mt1, fmaxf(c[ni][2], c[ni][3]));
        }
        mt0 = fmaxf(mt0, __shfl_xor_sync(0xffffffffu, mt0, 1));
        mt0 = fmaxf(mt0, __shfl_xor_sync(0xffffffffu, mt0, 2));
        mt1 = fmaxf(mt1, __shfl_xor_sync(0xffffffffu, mt1, 1));
        mt1 = fmaxf(mt1, __shfl_xor_sync(0xffffffffu, mt1, 2));

        const float mn0 = fmaxf(m0, mt0);
        const float mn1 = fmaxf(m1, mt1);
        const float al0 = __expf(m0 - mn0);
        const float al1 = __expf(m1 - mn1);
        m0 = mn0; m1 = mn1;

        float ps0 = 0.f, ps1 = 0.f;
        #pragma unroll
        for (int ni = 0; ni < 8; ni++) {
            c[ni][0] = __expf(c[ni][0] - mn0);
            c[ni][1] = __expf(c[ni][1] - mn0);
            c[ni][2] = __expf(c[ni][2] - mn1);
            c[ni][3] = __expf(c[ni][3] - mn1);
            ps0 += c[ni][0] + c[ni][1];
            ps1 += c[ni][2] + c[ni][3];
        }
        ps0 += __shfl_xor_sync(0xffffffffu, ps0, 1);
        ps0 += __shfl_xor_sync(0xffffffffu, ps0, 2);
        ps1 += __shfl_xor_sync(0xffffffffu, ps1, 1);
        ps1 += __shfl_xor_sync(0xffffffffu, ps1, 2);
        l0 = l0 * al0 + ps0;
        l1 = l1 * al1 + ps1;

        #pragma unroll
        for (int di = 0; di < 8; di++) {
            oacc[di][0] *= al0; oacc[di][1] *= al0;
            oacc[di][2] *= al1; oacc[di][3] *= al1;
        }

        #pragma unroll
        for (int st = 0; st < 4; st++) {
            uint32_t pa[4];
            pa[0] = pack_bf(c[2*st][0],   c[2*st][1]);
            pa[1] = pack_bf(c[2*st][2],   c[2*st][3]);
            pa[2] = pack_bf(c[2*st+1][0], c[2*st+1][1]);
            pa[3] = pack_bf(c[2*st+1][2], c[2*st+1][3]);
            #pragma unroll
            for (int di = 0; di < 8; di++) {
                const int nr = di * 8 + g;
                const int kc = st * 16 + tg * 2;
                uint32_t bf[2];
                bf[0] = *(const uint32_t*)&Vt[nr][kc];
                bf[1] = *(const uint32_t*)&Vt[nr][kc + 8];
                mma16816(oacc[di], pa, bf);
            }
        }
    }

    const float inv0 = 1.0f / l0;
    const float inv1 = 1.0f / l1;
    const size_t o0 = base + (size_t)qr0 * DD;
    const size_t o1 = o0 + 8 * DD;
    #pragma unroll
    for (int di = 0; di < 8; di++) {
        const int d = di * 8 + tg * 2;
        *(uint32_t*)(OF + o0 + d) = pack_hf(oacc[di][0] * inv0, oacc[di][1] * inv0);
        *(uint32_t*)(OF + o1 + d) = pack_hf(oacc[di][2] * inv1, oacc[di][3] * inv1);
    }
}

// ---------------- block reduction helper ------------------------------------
__device__ __forceinline__ float block_sum256(float v) {
    __shared__ float red[8];
    #pragma unroll
    for (int off = 16; off; off >>= 1)
        v += __shfl_xor_sync(0xffffffffu, v, off);
    if ((threadIdx.x & 31) == 0) red[threadIdx.x >> 5] = v;
    __syncthreads();
    if (threadIdx.x < 32) {
        float t = (threadIdx.x < 8) ? red[threadIdx.x] : 0.0f;
        #pragma unroll
        for (int off = 4; off; off >>= 1)
            t += __shfl_xor_sync(0xffffffffu, t, off);
        if (threadIdx.x == 0) red[0] = t;
    }
    __syncthreads();
    float r = red[0];
    __syncthreads();
    return r;
}

// ---------------- LayerNorm (writes fp16) ------------------------------------
__global__ __launch_bounds__(256)
void ln_kernel(const float* __restrict__ x, const float* __restrict__ g,
               const float* __restrict__ b, __half* __restrict__ oF)
{
    const int row = blockIdx.x;
    const int tid = threadIdx.x;
    const float* xr = x + (size_t)row * DD;
    float4 v = *(const float4*)(xr + tid * 4);

    float s = v.x + v.y + v.z + v.w;
    float mean = block_sum256(s) * (1.0f / DD);

    float dx = v.x - mean, dy = v.y - mean, dz = v.z - mean, dw = v.w - mean;
    float ss = dx*dx + dy*dy + dz*dz + dw*dw;
    float var = block_sum256(ss) * (1.0f / DD);
    float rstd = rsqrtf(var + 1e-5f);

    float4 gv = *(const float4*)(g + tid * 4);
    float4 bv = *(const float4*)(b + tid * 4);
    float4 ov;
    ov.x = dx * rstd * gv.x + bv.x;
    ov.y = dy * rstd * gv.y + bv.y;
    ov.z = dz * rstd * gv.z + bv.z;
    ov.w = dw * rstd * gv.w + bv.w;
    const size_t off = (size_t)row * DD + tid * 4;
    uint2 hh = { pack_hf(ov.x, ov.y), pack_hf(ov.z, ov.w) };
    *(uint2*)(oF + off) = hh;
}

// ---------------- RoPE -------------------------------------------------------
__global__ __launch_bounds__(256)
void rope_kernel(float* __restrict__ x)
{
    const int idx  = blockIdx.x * blockDim.x + threadIdx.x;
    const int pair = idx & 511;
    const int row  = idx >> 9;
    const int t    = row & (TT - 1);
    const int i    = pair & 31;
    const float ang = (float)t * expf(-0.28782313662425537f * (float)i);
    float s, c;
    sincosf(ang, &s, &c);
    float2* p = (float2*)(x + ((size_t)row << 10) + (pair << 1));
    float2 v = *p;
    float2 o;
    o.x = v.x * c - v.y * s;
    o.y = v.x * s + v.y * c;
    *p = o;
}

// ---------------- launch ----------------------------------------------------
extern "C" void kernel_launch(void* const* d_in, const int* in_sizes, int n_in,
                              void* d_out, int out_size)
{
    const float* x   = (const float*)d_in[0];
    const unsigned char* mask = (const unsigned char*)d_in[1];
    const float* Wq  = (const float*)d_in[2];
    const float* bq  = (const float*)d_in[3];
    const float* Wk  = (const float*)d_in[4];
    const float* bk  = (const float*)d_in[5];
    const float* Wv  = (const float*)d_in[6];
    const float* bv  = (const float*)d_in[7];
    const float* Wo  = (const float*)d_in[8];
    const float* bo  = (const float*)d_in[9];
    const float* W1  = (const float*)d_in[10];
    const float* b1  = (const float*)d_in[11];
    const float* W2  = (const float*)d_in[12];
    const float* b2  = (const float*)d_in[13];
    const float* g1  = (const float*)d_in[14];
    const float* be1 = (const float*)d_in[15];
    const float* g2  = (const float*)d_in[16];
    const float* be2 = (const float*)d_in[17];
    float* out = (float*)d_out;

    float *q, *k, *v, *x2;
    cudaGetSymbolAddress((void**)&q,  g_q);
    cudaGetSymbolAddress((void**)&k,  g_k);
    cudaGetSymbolAddress((void**)&v,  g_v);
    cudaGetSymbolAddress((void**)&x2, g_x2);

    __half *hF, *attF, *ffF, *WqF, *WkF, *WvF, *WoF, *W1F, *W2F;
    cudaGetSymbolAddress((void**)&hF,   g_hF);
    cudaGetSymbolAddress((void**)&attF, g_attF);
    cudaGetSymbolAddress((void**)&ffF,  g_ffF);
    cudaGetSymbolAddress((void**)&WqF,  g_WqF);
    cudaGetSymbolAddress((void**)&WkF,  g_WkF);
    cudaGetSymbolAddress((void**)&WvF,  g_WvF);
    cudaGetSymbolAddress((void**)&WoF,  g_WoF);
    cudaGetSymbolAddress((void**)&W1F,  g_W1F);
    cudaGetSymbolAddress((void**)&W2F,  g_W2F);

    cudaFuncSetAttribute(gemm_hf, cudaFuncAttributeMaxDynamicSharedMemorySize, GEMM_SMEM);

    const dim3 gD (DD  / BN, ROWS / BM);   // (8,64)
    const dim3 gDF(DFF / BN, ROWS / BM);   // (32,64)
    const int WD  = DD * DD / 4 / 256;
    const int WDF = DD * DFF / 4 / 256;

    // 0) weight conversions (cheap, memory-bound)
    convert_half<<<WD,  256>>>(Wq, WqF);
    convert_half<<<WD,  256>>>(Wk, WkF);
    convert_half<<<WD,  256>>>(Wv, WvF);
    convert_half<<<WD,  256>>>(Wo, WoF);
    convert_half<<<WDF, 256>>>(W1, W1F);
    convert_half<<<WDF, 256>>>(W2, W2F);

    // 1) h = LN(x)  (fp16)
    ln_kernel<<<ROWS, 256>>>(x, g1, be1, hF);
    // 2) q,k,v projections (fp32 out for rope/attention)
    gemm_hf<<<gD, 256, GEMM_SMEM>>>(hF, WqF, bq, nullptr, q, nullptr, DD, DD, 0);
    gemm_hf<<<gD, 256, GEMM_SMEM>>>(hF, WkF, bk, nullptr, k, nullptr, DD, DD, 0);
    gemm_hf<<<gD, 256, GEMM_SMEM>>>(hF, WvF, bv, nullptr, v, nullptr, DD, DD, 0);
    // 3) rope on q, k (in place)
    rope_kernel<<<(ROWS * DD / 2) / 256, 256>>>(q);
    rope_kernel<<<(ROWS * DD / 2) / 256, 256>>>(k);
    // 4) attention -> attF (fp16)
    attn_mma<<<dim3(TT / 64, NH, BB), 128>>>(q, k, v, mask, attF);
    // 5) x2 = x + att @ Wo^T + bo
    gemm_hf<<<gD, 256, GEMM_SMEM>>>(attF, WoF, bo, x, x2, nullptr, DD, DD, 0);
    // 6) h = LN(x2) (fp16)
    ln_kernel<<<ROWS, 256>>>(x2, g2, be2, hF);
    // 7) ff = gelu(h @ W1^T + b1) -> fp16
    gemm_hf<<<gDF, 256, GEMM_SMEM>>>(hF, W1F, b1, nullptr, nullptr, ffF, DFF, DD, 1);
    // 8) out = x2 + ff @ W2^T + b2
    gemm_hf<<<gD, 256, GEMM_SMEM>>>(ffF, W2F, b2, x2, out, nullptr, DD, DFF, 0);
}